// round 5
// baseline (speedup 1.0000x reference)
#include <cuda_runtime.h>
#include <cuda_bf16.h>
#include <stdint.h>

// ============================================================
// Problem dims
// ============================================================
#define IN_F  4096
#define OUT_F 4096
#define BATCH 8192

#define BM 256
#define BN 128
#define BK 32
#define NK (IN_F / BK)          // 128 k-tiles
#define NPM (BATCH / BM)        // 32
#define NPN (OUT_F / BN)        // 32
#define TILE_GROUP 8
#define THREADS 320             // 8 consumer warps (4x2, 64x64 tiles) + 2 producers
#define STAGES 4

#define NK8  (IN_F / 8)
#define NK16 (IN_F / 16)

// SMEM: [0..32) full mbar[4], [32..64) empty mbar[4], buffers at 128
#define SM_BUF0 128
#define SM_A_BYTES 32768
#define SM_B_BYTES 16384
#define STAGE_BYTES (SM_A_BYTES + SM_B_BYTES)        // 49152
#define SMEM_TOTAL (SM_BUF0 + STAGES * STAGE_BYTES)  // 196736

// ============================================================
// Scratch
// ============================================================
__device__ float4 g_XP[(size_t)(BATCH / 16) * NK8 * 32];
__device__ float4 g_WP[(size_t)(OUT_F / 8) * NK16 * 32];
__device__ float  g_bias[OUT_F];

// ============================================================
// Helpers
// ============================================================
__device__ __forceinline__ float rnd_tf32(float f) {
    float r;
    asm("cvt.rna.tf32.f32 %0, %1;" : "=f"(r) : "f"(f));
    return r;
}

__device__ __forceinline__ uint32_t smem_u32(const void* p) {
    uint32_t a;
    asm("{ .reg .u64 t; cvta.to.shared.u64 t, %1; cvt.u32.u64 %0, t; }"
        : "=r"(a) : "l"(p));
    return a;
}

__device__ __forceinline__ void cp16(uint32_t saddr, const void* gptr) {
    asm volatile("cp.async.cg.shared.global [%0], [%1], 16;\n"
                 :: "r"(saddr), "l"(gptr));
}

__device__ __forceinline__ void mbar_init(uint32_t a, uint32_t cnt) {
    asm volatile("mbarrier.init.shared.b64 [%0], %1;" :: "r"(a), "r"(cnt) : "memory");
}
__device__ __forceinline__ void mbar_arrive(uint32_t a) {
    asm volatile("mbarrier.arrive.shared.b64 _, [%0];" :: "r"(a) : "memory");
}
__device__ __forceinline__ void mbar_wait(uint32_t addr, uint32_t parity) {
    asm volatile(
        "{\n\t.reg .pred P;\n\t"
        "WAIT_%=:\n\t"
        "mbarrier.try_wait.parity.acquire.cta.shared::cta.b64 P, [%0], %1, 0x989680;\n\t"
        "@P bra.uni DONE_%=;\n\t"
        "bra.uni WAIT_%=;\n\t"
        "DONE_%=:\n\t}"
        :: "r"(addr), "r"(parity) : "memory");
}
// arrive on mbar when all prior cp.async of this thread have completed
__device__ __forceinline__ void cp_async_arrive(uint32_t a) {
    asm volatile("cp.async.mbarrier.arrive.noinc.shared.b64 [%0];"
                 :: "r"(a) : "memory");
}

__device__ __forceinline__ void mma_tf32(float& c0, float& c1, float& c2, float& c3,
                                         uint32_t a0, uint32_t a1, uint32_t a2, uint32_t a3,
                                         uint32_t b0, uint32_t b1) {
    asm volatile(
        "mma.sync.aligned.m16n8k8.row.col.f32.tf32.tf32.f32 "
        "{%0,%1,%2,%3}, {%4,%5,%6,%7}, {%8,%9}, {%0,%1,%2,%3};"
        : "+f"(c0), "+f"(c1), "+f"(c2), "+f"(c3)
        : "r"(a0), "r"(a1), "r"(a2), "r"(a3), "r"(b0), "r"(b1));
}

// ============================================================
// Prep: materialize + tf32-round + pack into fragment order
// ============================================================
__global__ void prep_x_pack(const float* __restrict__ x) {
    size_t i = (size_t)blockIdx.x * blockDim.x + threadIdx.x;  // 8388608
    int row16 = (int)(i >> 14);
    int rem   = (int)(i & 16383);
    int k8    = rem >> 5;
    int lane  = rem & 31;
    int g = lane >> 2, t = lane & 3;
    const float* p0 = x + (size_t)(row16 * 16 + g) * IN_F + k8 * 8 + t;
    float4 v;
    v.x = rnd_tf32(p0[0]);
    v.y = rnd_tf32(p0[8 * IN_F]);
    v.z = rnd_tf32(p0[4]);
    v.w = rnd_tf32(p0[8 * IN_F + 4]);
    g_XP[i] = v;
}

__global__ void prep_w_pack(const float* __restrict__ mu,
                            const float* __restrict__ lv,
                            const float* __restrict__ eps) {
    size_t i = (size_t)blockIdx.x * blockDim.x + threadIdx.x;  // 4194304
    int col8 = (int)(i >> 13);
    int rem  = (int)(i & 8191);
    int k16  = rem >> 5;
    int lane = rem & 31;
    int g = lane >> 2, t = lane & 3;
    size_t base = (size_t)(col8 * 8 + g) * IN_F + k16 * 16 + t;
    float4 v;
#pragma unroll
    for (int j = 0; j < 4; ++j) {
        size_t a = base + (j & 1) * 4 + (j >> 1) * 8;
        float w = mu[a] + eps[a] * __expf(0.5f * lv[a]);
        (&v.x)[j] = rnd_tf32(w);
    }
    g_WP[i] = v;
}

__global__ void prep_bias_kernel(const float* __restrict__ bmu,
                                 const float* __restrict__ blv,
                                 const float* __restrict__ beps) {
    int i = blockIdx.x * blockDim.x + threadIdx.x;
    if (i < OUT_F) g_bias[i] = bmu[i] + beps[i] * __expf(0.5f * blv[i]);
}

// ============================================================
// GEMM: C[256,128] per CTA. 8 consumer warps (64x64) + 2 producer warps.
// No __syncthreads in mainloop: mbarrier producer/consumer pipeline.
// ============================================================
__global__ void __launch_bounds__(THREADS, 1) gemm_kernel(float* __restrict__ out) {
    extern __shared__ char smem[];
    const uint32_t sb = smem_u32(smem);
    const int tid = threadIdx.x;
    const int wid = tid >> 5;
    const int lane = tid & 31;

    int pid = blockIdx.x;
    int grp = pid / (TILE_GROUP * NPN);
    int pin = pid % (TILE_GROUP * NPN);
    int pm  = grp * TILE_GROUP + (pin % TILE_GROUP);
    int pn  = pin / TILE_GROUP;
    const int m0 = pm * BM;
    const int n0 = pn * BN;
    const int m016 = m0 >> 4;
    const int n08  = n0 >> 3;

    // mbarriers: full[s] at sb + s*8 (count 64 = producer threads, noinc arrives)
    //            empty[s] at sb + 32 + s*8 (count 8 = one lane per consumer warp)
    if (tid == 0) {
#pragma unroll
        for (int s = 0; s < STAGES; ++s) {
            mbar_init(sb + s * 8, 64);
            mbar_init(sb + 32 + s * 8, 8);
        }
    }
    __syncthreads();

    if (wid >= 8) {
        // ================= PRODUCER (warps 8,9) =================
        const int pt = (wid - 8) * 32 + lane;      // 0..63
        int phase = 1;                              // flipped: first wait passes
        for (int kt = 0; kt < NK; ++kt) {
            const int s = kt & 3;
            mbar_wait(sb + 32 + s * 8, phase);      // wait empty[s]
            const uint32_t abase = sb + SM_BUF0 + (uint32_t)s * STAGE_BYTES;
            const uint32_t bbase = abase + SM_A_BYTES;
            const int kt4 = kt * 4;
            const int kt2 = kt * 2;
#pragma unroll
            for (int t = 0; t < 32; ++t) {          // A: 2048 chunks / 64 thr
                int ca = pt + t * 64;
                int r16l = ca >> 7;
                int inner = ca & 127;
                size_t gidx = ((size_t)(m016 + r16l) * NK8 + kt4 + (inner >> 5)) * 32
                              + (inner & 31);
                cp16(abase + (uint32_t)ca * 16u, g_XP + gidx);
            }
#pragma unroll
            for (int t = 0; t < 16; ++t) {          // B: 1024 chunks / 64 thr
                int cb = pt + t * 64;
                int c8l = cb >> 6;
                int inner = cb & 63;
                size_t gidx = ((size_t)(n08 + c8l) * NK16 + kt2 + (inner >> 5)) * 32
                              + (inner & 31);
                cp16(bbase + (uint32_t)cb * 16u, g_WP + gidx);
            }
            cp_async_arrive(sb + s * 8);            // full[s] on completion
            if (s == 3) phase ^= 1;
        }
        return;
    }

    // ================= CONSUMER (warps 0..7) =================
    const int wm = wid >> 1;      // 0..3  (M, 64 rows)
    const int wn = wid & 1;       // 0..1  (N, 64 cols)
    const int gq = lane >> 2;
    const int tg = lane & 3;

    float c[4][8][4];
#pragma unroll
    for (int mt = 0; mt < 4; ++mt)
#pragma unroll
        for (int nt = 0; nt < 8; ++nt)
#pragma unroll
            for (int j = 0; j < 4; ++j) c[mt][nt][j] = 0.0f;

    int phase = 0;
    for (int kt = 0; kt < NK; ++kt) {
        const int s = kt & 3;
        mbar_wait(sb + s * 8, phase);               // wait full[s]

        const float4* sA = reinterpret_cast<const float4*>(
            smem + SM_BUF0 + (size_t)s * STAGE_BYTES);
        const float4* sB = reinterpret_cast<const float4*>(
            smem + SM_BUF0 + (size_t)s * STAGE_BYTES + SM_A_BYTES);

#pragma unroll
        for (int k16 = 0; k16 < 2; ++k16) {
            float4 bf[8];
#pragma unroll
            for (int nt = 0; nt < 8; ++nt)
                bf[nt] = sB[(((wn * 8 + nt) * 2 + k16) * 32) + lane];
#pragma unroll
            for (int kk2 = 0; kk2 < 2; ++kk2) {
                const int kk = k16 * 2 + kk2;
                float4 af[4];
#pragma unroll
                for (int mt = 0; mt < 4; ++mt)
                    af[mt] = sA[(((wm * 4 + mt) * 4 + kk) * 32) + lane];
#pragma unroll
                for (int nt = 0; nt < 8; ++nt) {
                    uint32_t b0 = __float_as_uint(kk2 ? bf[nt].z : bf[nt].x);
                    uint32_t b1 = __float_as_uint(kk2 ? bf[nt].w : bf[nt].y);
#pragma unroll
                    for (int mt = 0; mt < 4; ++mt) {
                        mma_tf32(c[mt][nt][0], c[mt][nt][1], c[mt][nt][2], c[mt][nt][3],
                                 __float_as_uint(af[mt].x), __float_as_uint(af[mt].y),
                                 __float_as_uint(af[mt].z), __float_as_uint(af[mt].w),
                                 b0, b1);
                    }
                }
            }
        }

        if (lane == 0) mbar_arrive(sb + 32 + s * 8);   // empty[s]
        if (s == 3) phase ^= 1;
    }

    // ---- epilogue: bias + store ----
#pragma unroll
    for (int mt = 0; mt < 4; ++mt) {
        const int row0 = m0 + wm * 64 + mt * 16 + gq;
#pragma unroll
        for (int nt = 0; nt < 8; ++nt) {
            const int col = n0 + wn * 64 + nt * 8 + 2 * tg;
            const float2 bv = *reinterpret_cast<const float2*>(g_bias + col);
            float2 v0, v1;
            v0.x = c[mt][nt][0] + bv.x;
            v0.y = c[mt][nt][1] + bv.y;
            v1.x = c[mt][nt][2] + bv.x;
            v1.y = c[mt][nt][3] + bv.y;
            *reinterpret_cast<float2*>(out + (size_t)row0 * OUT_F + col) = v0;
            *reinterpret_cast<float2*>(out + (size_t)(row0 + 8) * OUT_F + col) = v1;
        }
    }
}

// ============================================================
// Launch
// ============================================================
extern "C" void kernel_launch(void* const* d_in, const int* in_sizes, int n_in,
                              void* d_out, int out_size) {
    const float* x    = (const float*)d_in[0];
    const float* wmu  = (const float*)d_in[1];
    const float* wlv  = (const float*)d_in[2];
    const float* bmu  = (const float*)d_in[3];
    const float* blv  = (const float*)d_in[4];
    const float* weps = (const float*)d_in[5];
    const float* beps = (const float*)d_in[6];
    float* out = (float*)d_out;

    prep_x_pack<<<32768, 256>>>(x);
    prep_w_pack<<<16384, 256>>>(wmu, wlv, weps);
    prep_bias_kernel<<<16, 256>>>(bmu, blv, beps);

    cudaFuncSetAttribute(gemm_kernel,
                         cudaFuncAttributeMaxDynamicSharedMemorySize, SMEM_TOTAL);
    gemm_kernel<<<NPM * NPN, THREADS, SMEM_TOTAL>>>(out);
}

// round 6
// speedup vs baseline: 1.2371x; 1.2371x over previous
#include <cuda_runtime.h>
#include <cuda_bf16.h>
#include <stdint.h>

// ============================================================
// Problem dims
// ============================================================
#define IN_F  4096
#define OUT_F 4096
#define BATCH 8192

#define BM 256
#define BN 128
#define BK 64
#define NK (IN_F / BK)          // 64 k-tiles
#define NPM (BATCH / BM)        // 32
#define NPN (OUT_F / BN)        // 32
#define TILE_GROUP 8
#define THREADS 256             // 8 warps: 4 (M) x 2 (N), warp tile 64x64
#define STAGES 2

#define NK8  (IN_F / 8)         // 512 k8 groups per row
#define NK16 (IN_F / 16)        // 256 k16 groups per row

// SMEM stage layout (packed fragment order):
//  A: 16 row16-groups x 8 k8 x 32 lanes x float4 = 65536 B
//  B: 16 col8-groups  x 4 k16 x 32 lanes x float4 = 32768 B
#define SM_A_BYTES 65536
#define SM_B_BYTES 32768
#define STAGE_BYTES (SM_A_BYTES + SM_B_BYTES)        // 98304
#define SMEM_TOTAL (STAGES * STAGE_BYTES)            // 196608

// ============================================================
// Scratch
// ============================================================
__device__ float4 g_XP[(size_t)(BATCH / 16) * NK8 * 32];
__device__ float4 g_WP[(size_t)(OUT_F / 8) * NK16 * 32];
__device__ float  g_bias[OUT_F];

// ============================================================
// Helpers
// ============================================================
__device__ __forceinline__ float rnd_tf32(float f) {
    float r;
    asm("cvt.rna.tf32.f32 %0, %1;" : "=f"(r) : "f"(f));
    return r;
}

__device__ __forceinline__ uint32_t smem_u32(const void* p) {
    uint32_t a;
    asm("{ .reg .u64 t; cvta.to.shared.u64 t, %1; cvt.u32.u64 %0, t; }"
        : "=r"(a) : "l"(p));
    return a;
}

__device__ __forceinline__ void cp16(uint32_t saddr, const void* gptr) {
    asm volatile("cp.async.cg.shared.global [%0], [%1], 16;\n"
                 :: "r"(saddr), "l"(gptr));
}
__device__ __forceinline__ void cp_commit() {
    asm volatile("cp.async.commit_group;\n" ::: "memory");
}
template <int N>
__device__ __forceinline__ void cp_wait() {
    asm volatile("cp.async.wait_group %0;\n" :: "n"(N) : "memory");
}

__device__ __forceinline__ void mma_tf32(float& c0, float& c1, float& c2, float& c3,
                                         uint32_t a0, uint32_t a1, uint32_t a2, uint32_t a3,
                                         uint32_t b0, uint32_t b1) {
    asm volatile(
        "mma.sync.aligned.m16n8k8.row.col.f32.tf32.tf32.f32 "
        "{%0,%1,%2,%3}, {%4,%5,%6,%7}, {%8,%9}, {%0,%1,%2,%3};"
        : "+f"(c0), "+f"(c1), "+f"(c2), "+f"(c3)
        : "r"(a0), "r"(a1), "r"(a2), "r"(a3), "r"(b0), "r"(b1));
}

// ============================================================
// Prep: materialize + tf32-round + pack into fragment order
// ============================================================
__global__ void prep_x_pack(const float* __restrict__ x) {
    size_t i = (size_t)blockIdx.x * blockDim.x + threadIdx.x;  // 8388608
    int row16 = (int)(i >> 14);
    int rem   = (int)(i & 16383);
    int k8    = rem >> 5;
    int lane  = rem & 31;
    int g = lane >> 2, t = lane & 3;
    const float* p0 = x + (size_t)(row16 * 16 + g) * IN_F + k8 * 8 + t;
    float4 v;
    v.x = rnd_tf32(p0[0]);
    v.y = rnd_tf32(p0[8 * IN_F]);
    v.z = rnd_tf32(p0[4]);
    v.w = rnd_tf32(p0[8 * IN_F + 4]);
    g_XP[i] = v;
}

__global__ void prep_w_pack(const float* __restrict__ mu,
                            const float* __restrict__ lv,
                            const float* __restrict__ eps) {
    size_t i = (size_t)blockIdx.x * blockDim.x + threadIdx.x;  // 4194304
    int col8 = (int)(i >> 13);
    int rem  = (int)(i & 8191);
    int k16  = rem >> 5;
    int lane = rem & 31;
    int g = lane >> 2, t = lane & 3;
    size_t base = (size_t)(col8 * 8 + g) * IN_F + k16 * 16 + t;
    float4 v;
#pragma unroll
    for (int j = 0; j < 4; ++j) {
        size_t a = base + (j & 1) * 4 + (j >> 1) * 8;
        float w = mu[a] + eps[a] * __expf(0.5f * lv[a]);
        (&v.x)[j] = rnd_tf32(w);
    }
    g_WP[i] = v;
}

__global__ void prep_bias_kernel(const float* __restrict__ bmu,
                                 const float* __restrict__ blv,
                                 const float* __restrict__ beps) {
    int i = blockIdx.x * blockDim.x + threadIdx.x;
    if (i < OUT_F) g_bias[i] = bmu[i] + beps[i] * __expf(0.5f * blv[i]);
}

// ============================================================
// GEMM: C[256,128] per CTA, 256 threads (8 warps = 4 x 2)
// warp tile 64 x 64, BK=64, 2-stage pipeline (96KB/stage)
// ============================================================
__global__ void __launch_bounds__(THREADS, 1) gemm_kernel(float* __restrict__ out) {
    extern __shared__ char smem[];
    const uint32_t sb = smem_u32(smem);
    const int tid = threadIdx.x;
    const int wid = tid >> 5;
    const int lane = tid & 31;
    const int wm = wid >> 1;      // 0..3  (M, 64 rows)
    const int wn = wid & 1;       // 0..1  (N, 64 cols)
    const int gq = lane >> 2;
    const int tg = lane & 3;

    int pid = blockIdx.x;
    int grp = pid / (TILE_GROUP * NPN);
    int pin = pid % (TILE_GROUP * NPN);
    int pm  = grp * TILE_GROUP + (pin % TILE_GROUP);
    int pn  = pin / TILE_GROUP;
    const int m0 = pm * BM;
    const int n0 = pn * BN;
    const int m016 = m0 >> 4;
    const int n08  = n0 >> 3;

    // ---- stage loader: 24 cp16/thread ----
    auto load_stage = [&](int s, int kt) {
        const uint32_t abase = sb + (uint32_t)s * STAGE_BYTES;
        const uint32_t bbase = abase + SM_A_BYTES;
        const int kt8 = kt * 8;   // k8 base
        const int kt4 = kt * 4;   // k16 base
#pragma unroll
        for (int t = 0; t < 16; ++t) {           // A: 4096 chunks
            int ca = tid + t * THREADS;
            int r16l = ca >> 8;                  // 256 chunks per row16 group
            int inner = ca & 255;                // k8l*32 + lane
            size_t gidx = ((size_t)(m016 + r16l) * NK8 + kt8 + (inner >> 5)) * 32
                          + (inner & 31);
            cp16(abase + (uint32_t)ca * 16u, g_XP + gidx);
        }
#pragma unroll
        for (int t = 0; t < 8; ++t) {            // B: 2048 chunks
            int cb = tid + t * THREADS;
            int c8l = cb >> 7;                   // 128 chunks per col8 group
            int inner = cb & 127;                // k16l*32 + lane
            size_t gidx = ((size_t)(n08 + c8l) * NK16 + kt4 + (inner >> 5)) * 32
                          + (inner & 31);
            cp16(bbase + (uint32_t)cb * 16u, g_WP + gidx);
        }
    };

    // prologue: fill both stages
    load_stage(0, 0); cp_commit();
    load_stage(1, 1); cp_commit();

    float c[4][8][4];
#pragma unroll
    for (int mt = 0; mt < 4; ++mt)
#pragma unroll
        for (int nt = 0; nt < 8; ++nt)
#pragma unroll
            for (int j = 0; j < 4; ++j) c[mt][nt][j] = 0.0f;

    for (int kt = 0; kt < NK; ++kt) {
        const int s = kt & 1;
        cp_wait<1>();            // stage kt resident
        __syncthreads();

        const float4* sA = reinterpret_cast<const float4*>(
            smem + (size_t)s * STAGE_BYTES);
        const float4* sB = reinterpret_cast<const float4*>(
            smem + (size_t)s * STAGE_BYTES + SM_A_BYTES);

#pragma unroll
        for (int k16 = 0; k16 < 4; ++k16) {
            float4 bf[8];
#pragma unroll
            for (int nt = 0; nt < 8; ++nt)
                bf[nt] = sB[(((wn * 8 + nt) * 4 + k16) * 32) + lane];
#pragma unroll
            for (int kk2 = 0; kk2 < 2; ++kk2) {
                const int kk = k16 * 2 + kk2;
                float4 af[4];
#pragma unroll
                for (int mt = 0; mt < 4; ++mt)
                    af[mt] = sA[(((wm * 4 + mt) * 8 + kk) * 32) + lane];
#pragma unroll
                for (int nt = 0; nt < 8; ++nt) {
                    uint32_t b0 = __float_as_uint(kk2 ? bf[nt].z : bf[nt].x);
                    uint32_t b1 = __float_as_uint(kk2 ? bf[nt].w : bf[nt].y);
#pragma unroll
                    for (int mt = 0; mt < 4; ++mt) {
                        mma_tf32(c[mt][nt][0], c[mt][nt][1], c[mt][nt][2], c[mt][nt][3],
                                 __float_as_uint(af[mt].x), __float_as_uint(af[mt].y),
                                 __float_as_uint(af[mt].z), __float_as_uint(af[mt].w),
                                 b0, b1);
                    }
                }
            }
        }

        // all warps done reading stage s -> safe to refill it
        __syncthreads();
        if (kt + 2 < NK) load_stage(s, kt + 2);
        cp_commit();
    }

    // ---- epilogue: bias + store ----
#pragma unroll
    for (int mt = 0; mt < 4; ++mt) {
        const int row0 = m0 + wm * 64 + mt * 16 + gq;
#pragma unroll
        for (int nt = 0; nt < 8; ++nt) {
            const int col = n0 + wn * 64 + nt * 8 + 2 * tg;
            const float2 bv = *reinterpret_cast<const float2*>(g_bias + col);
            float2 v0, v1;
            v0.x = c[mt][nt][0] + bv.x;
            v0.y = c[mt][nt][1] + bv.y;
            v1.x = c[mt][nt][2] + bv.x;
            v1.y = c[mt][nt][3] + bv.y;
            *reinterpret_cast<float2*>(out + (size_t)row0 * OUT_F + col) = v0;
            *reinterpret_cast<float2*>(out + (size_t)(row0 + 8) * OUT_F + col) = v1;
        }
    }
}

// ============================================================
// Launch
// ============================================================
extern "C" void kernel_launch(void* const* d_in, const int* in_sizes, int n_in,
                              void* d_out, int out_size) {
    const float* x    = (const float*)d_in[0];
    const float* wmu  = (const float*)d_in[1];
    const float* wlv  = (const float*)d_in[2];
    const float* bmu  = (const float*)d_in[3];
    const float* blv  = (const float*)d_in[4];
    const float* weps = (const float*)d_in[5];
    const float* beps = (const float*)d_in[6];
    float* out = (float*)d_out;

    prep_x_pack<<<32768, 256>>>(x);
    prep_w_pack<<<16384, 256>>>(wmu, wlv, weps);
    prep_bias_kernel<<<16, 256>>>(bmu, blv, beps);

    cudaFuncSetAttribute(gemm_kernel,
                         cudaFuncAttributeMaxDynamicSharedMemorySize, SMEM_TOTAL);
    gemm_kernel<<<NPM * NPN, THREADS, SMEM_TOTAL>>>(out);
}

// round 7
// speedup vs baseline: 1.2927x; 1.0449x over previous
#include <cuda_runtime.h>
#include <cuda_bf16.h>
#include <stdint.h>

// ============================================================
// Problem dims
// ============================================================
#define IN_F  4096
#define OUT_F 4096
#define BATCH 8192

#define BM 256
#define BN 128
#define BK 64
#define NK (IN_F / BK)          // 64 k-tiles
#define NPM (BATCH / BM)        // 32
#define NPN (OUT_F / BN)        // 32
#define TILE_GROUP 8
#define THREADS 256             // 8 warps: 4 (M) x 2 (N), warp tile 64x64
#define STAGES 2

#define NK8  (IN_F / 8)         // 512 k8 groups per row
#define NK16 (IN_F / 16)        // 256 k16 groups per row

// SMEM stage layout (packed fragment order):
//  A: 16 row16-groups x 8 k8 x 32 lanes x float4 = 65536 B
//  B: 16 col8-groups  x 4 k16 x 32 lanes x float4 = 32768 B
#define SM_A_BYTES 65536
#define SM_B_BYTES 32768
#define STAGE_BYTES (SM_A_BYTES + SM_B_BYTES)        // 98304
#define SMEM_TOTAL (STAGES * STAGE_BYTES)            // 196608

// ============================================================
// Scratch
// ============================================================
__device__ float4 g_XP[(size_t)(BATCH / 16) * NK8 * 32];
__device__ float4 g_WP[(size_t)(OUT_F / 8) * NK16 * 32];
__device__ float  g_bias[OUT_F];

// ============================================================
// Helpers
// ============================================================
__device__ __forceinline__ float rnd_tf32(float f) {
    float r;
    asm("cvt.rna.tf32.f32 %0, %1;" : "=f"(r) : "f"(f));
    return r;
}

__device__ __forceinline__ uint32_t smem_u32(const void* p) {
    uint32_t a;
    asm("{ .reg .u64 t; cvta.to.shared.u64 t, %1; cvt.u32.u64 %0, t; }"
        : "=r"(a) : "l"(p));
    return a;
}

__device__ __forceinline__ void cp16(uint32_t saddr, const void* gptr) {
    asm volatile("cp.async.cg.shared.global [%0], [%1], 16;\n"
                 :: "r"(saddr), "l"(gptr));
}
__device__ __forceinline__ void cp_commit() {
    asm volatile("cp.async.commit_group;\n" ::: "memory");
}
template <int N>
__device__ __forceinline__ void cp_wait() {
    asm volatile("cp.async.wait_group %0;\n" :: "n"(N) : "memory");
}

__device__ __forceinline__ void mma_tf32(float& c0, float& c1, float& c2, float& c3,
                                         uint32_t a0, uint32_t a1, uint32_t a2, uint32_t a3,
                                         uint32_t b0, uint32_t b1) {
    asm volatile(
        "mma.sync.aligned.m16n8k8.row.col.f32.tf32.tf32.f32 "
        "{%0,%1,%2,%3}, {%4,%5,%6,%7}, {%8,%9}, {%0,%1,%2,%3};"
        : "+f"(c0), "+f"(c1), "+f"(c2), "+f"(c3)
        : "r"(a0), "r"(a1), "r"(a2), "r"(a3), "r"(b0), "r"(b1));
}

// ============================================================
// Prep: materialize + tf32-round + pack into fragment order
// ============================================================
__global__ void prep_x_pack(const float* __restrict__ x) {
    size_t i = (size_t)blockIdx.x * blockDim.x + threadIdx.x;  // 8388608
    int row16 = (int)(i >> 14);
    int rem   = (int)(i & 16383);
    int k8    = rem >> 5;
    int lane  = rem & 31;
    int g = lane >> 2, t = lane & 3;
    const float* p0 = x + (size_t)(row16 * 16 + g) * IN_F + k8 * 8 + t;
    float4 v;
    v.x = rnd_tf32(p0[0]);
    v.y = rnd_tf32(p0[8 * IN_F]);
    v.z = rnd_tf32(p0[4]);
    v.w = rnd_tf32(p0[8 * IN_F + 4]);
    g_XP[i] = v;
}

__global__ void prep_w_pack(const float* __restrict__ mu,
                            const float* __restrict__ lv,
                            const float* __restrict__ eps) {
    size_t i = (size_t)blockIdx.x * blockDim.x + threadIdx.x;  // 4194304
    int col8 = (int)(i >> 13);
    int rem  = (int)(i & 8191);
    int k16  = rem >> 5;
    int lane = rem & 31;
    int g = lane >> 2, t = lane & 3;
    size_t base = (size_t)(col8 * 8 + g) * IN_F + k16 * 16 + t;
    float4 v;
#pragma unroll
    for (int j = 0; j < 4; ++j) {
        size_t a = base + (j & 1) * 4 + (j >> 1) * 8;
        float w = mu[a] + eps[a] * __expf(0.5f * lv[a]);
        (&v.x)[j] = rnd_tf32(w);
    }
    g_WP[i] = v;
}

__global__ void prep_bias_kernel(const float* __restrict__ bmu,
                                 const float* __restrict__ blv,
                                 const float* __restrict__ beps) {
    int i = blockIdx.x * blockDim.x + threadIdx.x;
    if (i < OUT_F) g_bias[i] = bmu[i] + beps[i] * __expf(0.5f * blv[i]);
}

// ============================================================
// GEMM: C[256,128] per CTA, 256 threads (8 warps = 4 x 2)
// warp tile 64 x 64, BK=64, 2-stage pipeline, refill interleaved
// into compute (one sync + one cp_wait per iteration).
// ============================================================
__global__ void __launch_bounds__(THREADS, 1) gemm_kernel(float* __restrict__ out) {
    extern __shared__ char smem[];
    const uint32_t sb = smem_u32(smem);
    const int tid = threadIdx.x;
    const int wid = tid >> 5;
    const int lane = tid & 31;
    const int wm = wid >> 1;      // 0..3  (M, 64 rows)
    const int wn = wid & 1;       // 0..1  (N, 64 cols)
    const int gq = lane >> 2;
    const int tg = lane & 3;

    int pid = blockIdx.x;
    int grp = pid / (TILE_GROUP * NPN);
    int pin = pid % (TILE_GROUP * NPN);
    int pm  = grp * TILE_GROUP + (pin % TILE_GROUP);
    int pn  = pin / TILE_GROUP;
    const int m0 = pm * BM;
    const int n0 = pn * BN;
    const int m016 = m0 >> 4;
    const int n08  = n0 >> 3;

    // ---- half-stage loaders: 12 cp16/thread each ----
    // half 0: A chunks t=0..11 ; half 1: A chunks t=12..15 + B chunks t=0..7
    auto load_half0 = [&](int s, int kt) {
        const uint32_t abase = sb + (uint32_t)s * STAGE_BYTES;
        const int kt8 = kt * 8;
#pragma unroll
        for (int t = 0; t < 12; ++t) {
            int ca = tid + t * THREADS;
            int r16l = ca >> 8;
            int inner = ca & 255;
            size_t gidx = ((size_t)(m016 + r16l) * NK8 + kt8 + (inner >> 5)) * 32
                          + (inner & 31);
            cp16(abase + (uint32_t)ca * 16u, g_XP + gidx);
        }
    };
    auto load_half1 = [&](int s, int kt) {
        const uint32_t abase = sb + (uint32_t)s * STAGE_BYTES;
        const uint32_t bbase = abase + SM_A_BYTES;
        const int kt8 = kt * 8;
        const int kt4 = kt * 4;
#pragma unroll
        for (int t = 12; t < 16; ++t) {
            int ca = tid + t * THREADS;
            int r16l = ca >> 8;
            int inner = ca & 255;
            size_t gidx = ((size_t)(m016 + r16l) * NK8 + kt8 + (inner >> 5)) * 32
                          + (inner & 31);
            cp16(abase + (uint32_t)ca * 16u, g_XP + gidx);
        }
#pragma unroll
        for (int t = 0; t < 8; ++t) {
            int cb = tid + t * THREADS;
            int c8l = cb >> 7;
            int inner = cb & 127;
            size_t gidx = ((size_t)(n08 + c8l) * NK16 + kt4 + (inner >> 5)) * 32
                          + (inner & 31);
            cp16(bbase + (uint32_t)cb * 16u, g_WP + gidx);
        }
    };

    // prologue: load stage 0 only (stage 1 loads during iter 0 compute)
    load_half0(0, 0);
    load_half1(0, 0);
    cp_commit();

    float c[4][8][4];
#pragma unroll
    for (int mt = 0; mt < 4; ++mt)
#pragma unroll
        for (int nt = 0; nt < 8; ++nt)
#pragma unroll
            for (int j = 0; j < 4; ++j) c[mt][nt][j] = 0.0f;

    for (int kt = 0; kt < NK; ++kt) {
        const int s = kt & 1;
        cp_wait<0>();            // stage kt resident (includes loads issued last iter)
        __syncthreads();         // also: all warps done reading stage 1-s

        const float4* sA = reinterpret_cast<const float4*>(
            smem + (size_t)s * STAGE_BYTES);
        const float4* sB = reinterpret_cast<const float4*>(
            smem + (size_t)s * STAGE_BYTES + SM_A_BYTES);

        const bool more = (kt + 1 < NK);

#pragma unroll
        for (int k16 = 0; k16 < 4; ++k16) {
            float4 bf[8];
#pragma unroll
            for (int nt = 0; nt < 8; ++nt)
                bf[nt] = sB[(((wn * 8 + nt) * 4 + k16) * 32) + lane];
#pragma unroll
            for (int kk2 = 0; kk2 < 2; ++kk2) {
                const int kk = k16 * 2 + kk2;
                float4 af[4];
#pragma unroll
                for (int mt = 0; mt < 4; ++mt)
                    af[mt] = sA[(((wm * 4 + mt) * 8 + kk) * 32) + lane];
#pragma unroll
                for (int nt = 0; nt < 8; ++nt) {
                    uint32_t b0 = __float_as_uint(kk2 ? bf[nt].z : bf[nt].x);
                    uint32_t b1 = __float_as_uint(kk2 ? bf[nt].w : bf[nt].y);
#pragma unroll
                    for (int mt = 0; mt < 4; ++mt) {
                        mma_tf32(c[mt][nt][0], c[mt][nt][1], c[mt][nt][2], c[mt][nt][3],
                                 __float_as_uint(af[mt].x), __float_as_uint(af[mt].y),
                                 __float_as_uint(af[mt].z), __float_as_uint(af[mt].w),
                                 b0, b1);
                    }
                }
            }
            // interleave next-stage refill under queued tensor work
            if (k16 == 0 && more) load_half0(1 - s, kt + 1);
            if (k16 == 1 && more) load_half1(1 - s, kt + 1);
        }

        cp_commit();
    }

    // ---- epilogue: bias + store ----
#pragma unroll
    for (int mt = 0; mt < 4; ++mt) {
        const int row0 = m0 + wm * 64 + mt * 16 + gq;
#pragma unroll
        for (int nt = 0; nt < 8; ++nt) {
            const int col = n0 + wn * 64 + nt * 8 + 2 * tg;
            const float2 bv = *reinterpret_cast<const float2*>(g_bias + col);
            float2 v0, v1;
            v0.x = c[mt][nt][0] + bv.x;
            v0.y = c[mt][nt][1] + bv.y;
            v1.x = c[mt][nt][2] + bv.x;
            v1.y = c[mt][nt][3] + bv.y;
            *reinterpret_cast<float2*>(out + (size_t)row0 * OUT_F + col) = v0;
            *reinterpret_cast<float2*>(out + (size_t)(row0 + 8) * OUT_F + col) = v1;
        }
    }
}

// ============================================================
// Launch
// ============================================================
extern "C" void kernel_launch(void* const* d_in, const int* in_sizes, int n_in,
                              void* d_out, int out_size) {
    const float* x    = (const float*)d_in[0];
    const float* wmu  = (const float*)d_in[1];
    const float* wlv  = (const float*)d_in[2];
    const float* bmu  = (const float*)d_in[3];
    const float* blv  = (const float*)d_in[4];
    const float* weps = (const float*)d_in[5];
    const float* beps = (const float*)d_in[6];
    float* out = (float*)d_out;

    prep_x_pack<<<32768, 256>>>(x);
    prep_w_pack<<<16384, 256>>>(wmu, wlv, weps);
    prep_bias_kernel<<<16, 256>>>(bmu, blv, beps);

    cudaFuncSetAttribute(gemm_kernel,
                         cudaFuncAttributeMaxDynamicSharedMemorySize, SMEM_TOTAL);
    gemm_kernel<<<NPM * NPN, THREADS, SMEM_TOTAL>>>(out);
}

// round 8
// speedup vs baseline: 1.3874x; 1.0733x over previous
#include <cuda_runtime.h>
#include <cuda_bf16.h>
#include <stdint.h>

// ============================================================
// Problem dims
// ============================================================
#define IN_F  4096
#define OUT_F 4096
#define BATCH 8192

#define BM 256
#define BN 128
#define BK 64
#define NK (IN_F / BK)          // 64 k-tiles
#define NPM (BATCH / BM)        // 32
#define NPN (OUT_F / BN)        // 32
#define TILE_GROUP 8
#define THREADS 256             // 8 warps: 4 (M) x 2 (N), warp tile 64x64
#define STAGES 2

#define NK8  (IN_F / 8)         // 512 k8 groups per row
#define NK16 (IN_F / 16)        // 256 k16 groups per row

// SMEM: [0..16) full mbar[2], [16..32) empty mbar[2], buffers at 128
#define SM_BUF0 128
#define SM_A_BYTES 65536
#define SM_B_BYTES 32768
#define STAGE_BYTES (SM_A_BYTES + SM_B_BYTES)        // 98304
#define SMEM_TOTAL (SM_BUF0 + STAGES * STAGE_BYTES)  // 196736

// ============================================================
// Scratch
// ============================================================
__device__ float4 g_XP[(size_t)(BATCH / 16) * NK8 * 32];
__device__ float4 g_WP[(size_t)(OUT_F / 8) * NK16 * 32];
__device__ float  g_bias[OUT_F];

// ============================================================
// Helpers
// ============================================================
__device__ __forceinline__ float rnd_tf32(float f) {
    float r;
    asm("cvt.rna.tf32.f32 %0, %1;" : "=f"(r) : "f"(f));
    return r;
}

__device__ __forceinline__ uint32_t smem_u32(const void* p) {
    uint32_t a;
    asm("{ .reg .u64 t; cvta.to.shared.u64 t, %1; cvt.u32.u64 %0, t; }"
        : "=r"(a) : "l"(p));
    return a;
}

__device__ __forceinline__ void cp16(uint32_t saddr, const void* gptr) {
    asm volatile("cp.async.cg.shared.global [%0], [%1], 16;\n"
                 :: "r"(saddr), "l"(gptr));
}

__device__ __forceinline__ void mbar_init(uint32_t a, uint32_t cnt) {
    asm volatile("mbarrier.init.shared.b64 [%0], %1;" :: "r"(a), "r"(cnt) : "memory");
}
__device__ __forceinline__ void mbar_arrive(uint32_t a) {
    asm volatile("mbarrier.arrive.shared.b64 _, [%0];" :: "r"(a) : "memory");
}
__device__ __forceinline__ void mbar_wait(uint32_t addr, uint32_t parity) {
    asm volatile(
        "{\n\t.reg .pred P;\n\t"
        "WAIT_%=:\n\t"
        "mbarrier.try_wait.parity.acquire.cta.shared::cta.b64 P, [%0], %1, 0x989680;\n\t"
        "@P bra.uni DONE_%=;\n\t"
        "bra.uni WAIT_%=;\n\t"
        "DONE_%=:\n\t}"
        :: "r"(addr), "r"(parity) : "memory");
}
// signal mbar when all prior cp.async of this thread have completed
__device__ __forceinline__ void cp_async_arrive(uint32_t a) {
    asm volatile("cp.async.mbarrier.arrive.noinc.shared.b64 [%0];"
                 :: "r"(a) : "memory");
}

__device__ __forceinline__ void mma_tf32(float& c0, float& c1, float& c2, float& c3,
                                         uint32_t a0, uint32_t a1, uint32_t a2, uint32_t a3,
                                         uint32_t b0, uint32_t b1) {
    asm volatile(
        "mma.sync.aligned.m16n8k8.row.col.f32.tf32.tf32.f32 "
        "{%0,%1,%2,%3}, {%4,%5,%6,%7}, {%8,%9}, {%0,%1,%2,%3};"
        : "+f"(c0), "+f"(c1), "+f"(c2), "+f"(c3)
        : "r"(a0), "r"(a1), "r"(a2), "r"(a3), "r"(b0), "r"(b1));
}

// ============================================================
// Prep: materialize + tf32-round + pack into fragment order
// ============================================================
__global__ void prep_x_pack(const float* __restrict__ x) {
    size_t i = (size_t)blockIdx.x * blockDim.x + threadIdx.x;  // 8388608
    int row16 = (int)(i >> 14);
    int rem   = (int)(i & 16383);
    int k8    = rem >> 5;
    int lane  = rem & 31;
    int g = lane >> 2, t = lane & 3;
    const float* p0 = x + (size_t)(row16 * 16 + g) * IN_F + k8 * 8 + t;
    float4 v;
    v.x = rnd_tf32(p0[0]);
    v.y = rnd_tf32(p0[8 * IN_F]);
    v.z = rnd_tf32(p0[4]);
    v.w = rnd_tf32(p0[8 * IN_F + 4]);
    g_XP[i] = v;
}

__global__ void prep_w_pack(const float* __restrict__ mu,
                            const float* __restrict__ lv,
                            const float* __restrict__ eps) {
    size_t i = (size_t)blockIdx.x * blockDim.x + threadIdx.x;  // 4194304
    int col8 = (int)(i >> 13);
    int rem  = (int)(i & 8191);
    int k16  = rem >> 5;
    int lane = rem & 31;
    int g = lane >> 2, t = lane & 3;
    size_t base = (size_t)(col8 * 8 + g) * IN_F + k16 * 16 + t;
    float4 v;
#pragma unroll
    for (int j = 0; j < 4; ++j) {
        size_t a = base + (j & 1) * 4 + (j >> 1) * 8;
        float w = mu[a] + eps[a] * __expf(0.5f * lv[a]);
        (&v.x)[j] = rnd_tf32(w);
    }
    g_WP[i] = v;
}

__global__ void prep_bias_kernel(const float* __restrict__ bmu,
                                 const float* __restrict__ blv,
                                 const float* __restrict__ beps) {
    int i = blockIdx.x * blockDim.x + threadIdx.x;
    if (i < OUT_F) g_bias[i] = bmu[i] + beps[i] * __expf(0.5f * blv[i]);
}

// ============================================================
// GEMM: C[256,128] per CTA, 256 threads (8 warps = 4 x 2)
// warp tile 64 x 64, BK=64, 2-stage pipeline. No __syncthreads in
// mainloop: stage-scoped mbarriers (full: cp-async completion of all
// 256 threads; empty: 8 warp read-done arrivals) let warps drift.
// ============================================================
__global__ void __launch_bounds__(THREADS, 1) gemm_kernel(float* __restrict__ out) {
    extern __shared__ char smem[];
    const uint32_t sb = smem_u32(smem);
    const int tid = threadIdx.x;
    const int wid = tid >> 5;
    const int lane = tid & 31;
    const int wm = wid >> 1;      // 0..3  (M, 64 rows)
    const int wn = wid & 1;       // 0..1  (N, 64 cols)
    const int gq = lane >> 2;
    const int tg = lane & 3;

    int pid = blockIdx.x;
    int grp = pid / (TILE_GROUP * NPN);
    int pin = pid % (TILE_GROUP * NPN);
    int pm  = grp * TILE_GROUP + (pin % TILE_GROUP);
    int pn  = pin / TILE_GROUP;
    const int m0 = pm * BM;
    const int n0 = pn * BN;
    const int m016 = m0 >> 4;
    const int n08  = n0 >> 3;

    // full[s] at sb + s*8, empty[s] at sb + 16 + s*8
    if (tid == 0) {
        mbar_init(sb + 0, 256); mbar_init(sb + 8, 256);
        mbar_init(sb + 16, 8);  mbar_init(sb + 24, 8);
    }
    __syncthreads();

    // ---- half-stage loaders: 12 cp16/thread each ----
    auto load_half0 = [&](int s, int kt) {
        const uint32_t abase = sb + SM_BUF0 + (uint32_t)s * STAGE_BYTES;
        const int kt8 = kt * 8;
#pragma unroll
        for (int t = 0; t < 12; ++t) {
            int ca = tid + t * THREADS;
            int r16l = ca >> 8;
            int inner = ca & 255;
            size_t gidx = ((size_t)(m016 + r16l) * NK8 + kt8 + (inner >> 5)) * 32
                          + (inner & 31);
            cp16(abase + (uint32_t)ca * 16u, g_XP + gidx);
        }
    };
    auto load_half1 = [&](int s, int kt) {
        const uint32_t abase = sb + SM_BUF0 + (uint32_t)s * STAGE_BYTES;
        const uint32_t bbase = abase + SM_A_BYTES;
        const int kt8 = kt * 8;
        const int kt4 = kt * 4;
#pragma unroll
        for (int t = 12; t < 16; ++t) {
            int ca = tid + t * THREADS;
            int r16l = ca >> 8;
            int inner = ca & 255;
            size_t gidx = ((size_t)(m016 + r16l) * NK8 + kt8 + (inner >> 5)) * 32
                          + (inner & 31);
            cp16(abase + (uint32_t)ca * 16u, g_XP + gidx);
        }
#pragma unroll
        for (int t = 0; t < 8; ++t) {
            int cb = tid + t * THREADS;
            int c8l = cb >> 7;
            int inner = cb & 127;
            size_t gidx = ((size_t)(n08 + c8l) * NK16 + kt4 + (inner >> 5)) * 32
                          + (inner & 31);
            cp16(bbase + (uint32_t)cb * 16u, g_WP + gidx);
        }
    };

    // prologue: load stage 0, signal full[0]
    load_half0(0, 0);
    load_half1(0, 0);
    cp_async_arrive(sb + 0);

    float c[4][8][4];
#pragma unroll
    for (int mt = 0; mt < 4; ++mt)
#pragma unroll
        for (int nt = 0; nt < 8; ++nt)
#pragma unroll
            for (int j = 0; j < 4; ++j) c[mt][nt][j] = 0.0f;

    for (int kt = 0; kt < NK; ++kt) {
        const int s = kt & 1;
        mbar_wait(sb + s * 8, (uint32_t)((kt >> 1) & 1));   // full[s]

        const float4* sA = reinterpret_cast<const float4*>(
            smem + SM_BUF0 + (size_t)s * STAGE_BYTES);
        const float4* sB = reinterpret_cast<const float4*>(
            smem + SM_BUF0 + (size_t)s * STAGE_BYTES + SM_A_BYTES);

        const bool more = (kt + 1 < NK);

#pragma unroll
        for (int k16 = 0; k16 < 4; ++k16) {
            float4 bf[8];
#pragma unroll
            for (int nt = 0; nt < 8; ++nt)
                bf[nt] = sB[(((wn * 8 + nt) * 4 + k16) * 32) + lane];
#pragma unroll
            for (int kk2 = 0; kk2 < 2; ++kk2) {
                const int kk = k16 * 2 + kk2;
                float4 af[4];
#pragma unroll
                for (int mt = 0; mt < 4; ++mt)
                    af[mt] = sA[(((wm * 4 + mt) * 8 + kk) * 32) + lane];
#pragma unroll
                for (int nt = 0; nt < 8; ++nt) {
                    uint32_t b0 = __float_as_uint(kk2 ? bf[nt].z : bf[nt].x);
                    uint32_t b1 = __float_as_uint(kk2 ? bf[nt].w : bf[nt].y);
#pragma unroll
                    for (int mt = 0; mt < 4; ++mt) {
                        mma_tf32(c[mt][nt][0], c[mt][nt][1], c[mt][nt][2], c[mt][nt][3],
                                 __float_as_uint(af[mt].x), __float_as_uint(af[mt].y),
                                 __float_as_uint(af[mt].z), __float_as_uint(af[mt].w),
                                 b0, b1);
                    }
                }
            }
            // interleaved refill of stage 1-s for kt+1
            if (k16 == 0 && more) {
                if (kt > 0)   // empty[1-s]: all warps done reading it (iter kt-1)
                    mbar_wait(sb + 16 + (1 - s) * 8,
                              (uint32_t)(((kt - 1) >> 1) & 1));
                load_half0(1 - s, kt + 1);
            }
            if (k16 == 1 && more) {
                load_half1(1 - s, kt + 1);
                cp_async_arrive(sb + (1 - s) * 8);   // full[1-s]
            }
        }

        // this warp finished all reads of stage s
        if (lane == 0) mbar_arrive(sb + 16 + s * 8);         // empty[s]
    }

    // ---- epilogue: bias + store ----
#pragma unroll
    for (int mt = 0; mt < 4; ++mt) {
        const int row0 = m0 + wm * 64 + mt * 16 + gq;
#pragma unroll
        for (int nt = 0; nt < 8; ++nt) {
            const int col = n0 + wn * 64 + nt * 8 + 2 * tg;
            const float2 bv = *reinterpret_cast<const float2*>(g_bias + col);
            float2 v0, v1;
            v0.x = c[mt][nt][0] + bv.x;
            v0.y = c[mt][nt][1] + bv.y;
            v1.x = c[mt][nt][2] + bv.x;
            v1.y = c[mt][nt][3] + bv.y;
            *reinterpret_cast<float2*>(out + (size_t)row0 * OUT_F + col) = v0;
            *reinterpret_cast<float2*>(out + (size_t)(row0 + 8) * OUT_F + col) = v1;
        }
    }
}

// ============================================================
// Launch
// ============================================================
extern "C" void kernel_launch(void* const* d_in, const int* in_sizes, int n_in,
                              void* d_out, int out_size) {
    const float* x    = (const float*)d_in[0];
    const float* wmu  = (const float*)d_in[1];
    const float* wlv  = (const float*)d_in[2];
    const float* bmu  = (const float*)d_in[3];
    const float* blv  = (const float*)d_in[4];
    const float* weps = (const float*)d_in[5];
    const float* beps = (const float*)d_in[6];
    float* out = (float*)d_out;

    prep_x_pack<<<32768, 256>>>(x);
    prep_w_pack<<<16384, 256>>>(wmu, wlv, weps);
    prep_bias_kernel<<<16, 256>>>(bmu, blv, beps);

    cudaFuncSetAttribute(gemm_kernel,
                         cudaFuncAttributeMaxDynamicSharedMemorySize, SMEM_TOTAL);
    gemm_kernel<<<NPM * NPN, THREADS, SMEM_TOTAL>>>(out);
}

// round 9
// speedup vs baseline: 1.3956x; 1.0058x over previous
#include <cuda_runtime.h>
#include <cuda_bf16.h>
#include <stdint.h>

// ============================================================
// Problem dims
// ============================================================
#define IN_F  4096
#define OUT_F 4096
#define BATCH 8192

#define BM 256
#define BN 128
#define BK 64
#define NK (IN_F / BK)          // 64 k-tiles
#define NPM (BATCH / BM)        // 32
#define NPN (OUT_F / BN)        // 32
#define TILE_GROUP 8
#define THREADS 256             // 8 warps: 4 (M) x 2 (N), warp tile 64x64
#define STAGES 2

#define NK8  (IN_F / 8)         // 512 k8 groups per row
#define NK16 (IN_F / 16)        // 256 k16 groups per row

// SMEM: [0..16) full mbar[2], [16..32) empty mbar[2], buffers at 128
#define SM_BUF0 128
#define SM_A_BYTES 65536
#define SM_B_BYTES 32768
#define STAGE_BYTES (SM_A_BYTES + SM_B_BYTES)        // 98304
#define SMEM_TOTAL (SM_BUF0 + STAGES * STAGE_BYTES)  // 196736

// ============================================================
// Scratch
// ============================================================
__device__ float4 g_XP[(size_t)(BATCH / 16) * NK8 * 32];
__device__ float4 g_WP[(size_t)(OUT_F / 8) * NK16 * 32];
__device__ float  g_bias[OUT_F];

// ============================================================
// Helpers
// ============================================================
__device__ __forceinline__ float rnd_tf32(float f) {
    float r;
    asm("cvt.rna.tf32.f32 %0, %1;" : "=f"(r) : "f"(f));
    return r;
}

__device__ __forceinline__ uint32_t smem_u32(const void* p) {
    uint32_t a;
    asm("{ .reg .u64 t; cvta.to.shared.u64 t, %1; cvt.u32.u64 %0, t; }"
        : "=r"(a) : "l"(p));
    return a;
}

__device__ __forceinline__ void cp16(uint32_t saddr, const void* gptr) {
    asm volatile("cp.async.cg.shared.global [%0], [%1], 16;\n"
                 :: "r"(saddr), "l"(gptr));
}

__device__ __forceinline__ void mbar_init(uint32_t a, uint32_t cnt) {
    asm volatile("mbarrier.init.shared.b64 [%0], %1;" :: "r"(a), "r"(cnt) : "memory");
}
__device__ __forceinline__ void mbar_arrive(uint32_t a) {
    asm volatile("mbarrier.arrive.shared.b64 _, [%0];" :: "r"(a) : "memory");
}
__device__ __forceinline__ void mbar_wait(uint32_t addr, uint32_t parity) {
    asm volatile(
        "{\n\t.reg .pred P;\n\t"
        "WAIT_%=:\n\t"
        "mbarrier.try_wait.parity.acquire.cta.shared::cta.b64 P, [%0], %1, 0x989680;\n\t"
        "@P bra.uni DONE_%=;\n\t"
        "bra.uni WAIT_%=;\n\t"
        "DONE_%=:\n\t}"
        :: "r"(addr), "r"(parity) : "memory");
}
// signal mbar when all prior cp.async of this thread have completed
__device__ __forceinline__ void cp_async_arrive(uint32_t a) {
    asm volatile("cp.async.mbarrier.arrive.noinc.shared.b64 [%0];"
                 :: "r"(a) : "memory");
}

__device__ __forceinline__ void mma_tf32(float& c0, float& c1, float& c2, float& c3,
                                         uint32_t a0, uint32_t a1, uint32_t a2, uint32_t a3,
                                         uint32_t b0, uint32_t b1) {
    asm volatile(
        "mma.sync.aligned.m16n8k8.row.col.f32.tf32.tf32.f32 "
        "{%0,%1,%2,%3}, {%4,%5,%6,%7}, {%8,%9}, {%0,%1,%2,%3};"
        : "+f"(c0), "+f"(c1), "+f"(c2), "+f"(c3)
        : "r"(a0), "r"(a1), "r"(a2), "r"(a3), "r"(b0), "r"(b1));
}

// ============================================================
// Prep: materialize + tf32-round + pack into fragment order
// ============================================================
__global__ void prep_x_pack(const float* __restrict__ x) {
    size_t i = (size_t)blockIdx.x * blockDim.x + threadIdx.x;  // 8388608
    int row16 = (int)(i >> 14);
    int rem   = (int)(i & 16383);
    int k8    = rem >> 5;
    int lane  = rem & 31;
    int g = lane >> 2, t = lane & 3;
    const float* p0 = x + (size_t)(row16 * 16 + g) * IN_F + k8 * 8 + t;
    float4 v;
    v.x = rnd_tf32(p0[0]);
    v.y = rnd_tf32(p0[8 * IN_F]);
    v.z = rnd_tf32(p0[4]);
    v.w = rnd_tf32(p0[8 * IN_F + 4]);
    g_XP[i] = v;
}

__global__ void prep_w_pack(const float* __restrict__ mu,
                            const float* __restrict__ lv,
                            const float* __restrict__ eps) {
    size_t i = (size_t)blockIdx.x * blockDim.x + threadIdx.x;  // 4194304
    int col8 = (int)(i >> 13);
    int rem  = (int)(i & 8191);
    int k16  = rem >> 5;
    int lane = rem & 31;
    int g = lane >> 2, t = lane & 3;
    size_t base = (size_t)(col8 * 8 + g) * IN_F + k16 * 16 + t;
    float4 v;
#pragma unroll
    for (int j = 0; j < 4; ++j) {
        size_t a = base + (j & 1) * 4 + (j >> 1) * 8;
        float w = mu[a] + eps[a] * __expf(0.5f * lv[a]);
        (&v.x)[j] = rnd_tf32(w);
    }
    g_WP[i] = v;
}

__global__ void prep_bias_kernel(const float* __restrict__ bmu,
                                 const float* __restrict__ blv,
                                 const float* __restrict__ beps) {
    int i = blockIdx.x * blockDim.x + threadIdx.x;
    if (i < OUT_F) g_bias[i] = bmu[i] + beps[i] * __expf(0.5f * blv[i]);
}

// ============================================================
// GEMM: C[256,128] per CTA, 256 threads (8 warps = 4 x 2)
// warp tile 64 x 64, BK=64, 2-stage pipeline. No __syncthreads in
// mainloop: stage-scoped mbarriers (full: cp-async completion of all
// 256 threads; empty: 8 warp read-done arrivals) let warps drift.
// ============================================================
__global__ void __launch_bounds__(THREADS, 1) gemm_kernel(float* __restrict__ out) {
    extern __shared__ char smem[];
    const uint32_t sb = smem_u32(smem);
    const int tid = threadIdx.x;
    const int wid = tid >> 5;
    const int lane = tid & 31;
    const int wm = wid >> 1;      // 0..3  (M, 64 rows)
    const int wn = wid & 1;       // 0..1  (N, 64 cols)
    const int gq = lane >> 2;
    const int tg = lane & 3;

    int pid = blockIdx.x;
    int grp = pid / (TILE_GROUP * NPN);
    int pin = pid % (TILE_GROUP * NPN);
    int pm  = grp * TILE_GROUP + (pin % TILE_GROUP);
    int pn  = pin / TILE_GROUP;
    const int m0 = pm * BM;
    const int n0 = pn * BN;
    const int m016 = m0 >> 4;
    const int n08  = n0 >> 3;

    // full[s] at sb + s*8, empty[s] at sb + 16 + s*8
    if (tid == 0) {
        mbar_init(sb + 0, 256); mbar_init(sb + 8, 256);
        mbar_init(sb + 16, 8);  mbar_init(sb + 24, 8);
    }
    __syncthreads();

    // ---- half-stage loaders: 12 cp16/thread each ----
    auto load_half0 = [&](int s, int kt) {
        const uint32_t abase = sb + SM_BUF0 + (uint32_t)s * STAGE_BYTES;
        const int kt8 = kt * 8;
#pragma unroll
        for (int t = 0; t < 12; ++t) {
            int ca = tid + t * THREADS;
            int r16l = ca >> 8;
            int inner = ca & 255;
            size_t gidx = ((size_t)(m016 + r16l) * NK8 + kt8 + (inner >> 5)) * 32
                          + (inner & 31);
            cp16(abase + (uint32_t)ca * 16u, g_XP + gidx);
        }
    };
    auto load_half1 = [&](int s, int kt) {
        const uint32_t abase = sb + SM_BUF0 + (uint32_t)s * STAGE_BYTES;
        const uint32_t bbase = abase + SM_A_BYTES;
        const int kt8 = kt * 8;
        const int kt4 = kt * 4;
#pragma unroll
        for (int t = 12; t < 16; ++t) {
            int ca = tid + t * THREADS;
            int r16l = ca >> 8;
            int inner = ca & 255;
            size_t gidx = ((size_t)(m016 + r16l) * NK8 + kt8 + (inner >> 5)) * 32
                          + (inner & 31);
            cp16(abase + (uint32_t)ca * 16u, g_XP + gidx);
        }
#pragma unroll
        for (int t = 0; t < 8; ++t) {
            int cb = tid + t * THREADS;
            int c8l = cb >> 7;
            int inner = cb & 127;
            size_t gidx = ((size_t)(n08 + c8l) * NK16 + kt4 + (inner >> 5)) * 32
                          + (inner & 31);
            cp16(bbase + (uint32_t)cb * 16u, g_WP + gidx);
        }
    };

    // prologue: load stage 0, signal full[0]
    load_half0(0, 0);
    load_half1(0, 0);
    cp_async_arrive(sb + 0);

    float c[4][8][4];
#pragma unroll
    for (int mt = 0; mt < 4; ++mt)
#pragma unroll
        for (int nt = 0; nt < 8; ++nt)
#pragma unroll
            for (int j = 0; j < 4; ++j) c[mt][nt][j] = 0.0f;

    for (int kt = 0; kt < NK; ++kt) {
        const int s = kt & 1;
        mbar_wait(sb + s * 8, (uint32_t)((kt >> 1) & 1));   // full[s]

        const float4* sA = reinterpret_cast<const float4*>(
            smem + SM_BUF0 + (size_t)s * STAGE_BYTES);
        const float4* sB = reinterpret_cast<const float4*>(
            smem + SM_BUF0 + (size_t)s * STAGE_BYTES + SM_A_BYTES);

        const bool more = (kt + 1 < NK);

#pragma unroll
        for (int k16 = 0; k16 < 4; ++k16) {
            float4 bf[8];
#pragma unroll
            for (int nt = 0; nt < 8; ++nt)
                bf[nt] = sB[(((wn * 8 + nt) * 4 + k16) * 32) + lane];
#pragma unroll
            for (int kk2 = 0; kk2 < 2; ++kk2) {
                const int kk = k16 * 2 + kk2;
                float4 af[4];
#pragma unroll
                for (int mt = 0; mt < 4; ++mt)
                    af[mt] = sA[(((wm * 4 + mt) * 8 + kk) * 32) + lane];
#pragma unroll
                for (int nt = 0; nt < 8; ++nt) {
                    uint32_t b0 = __float_as_uint(kk2 ? bf[nt].z : bf[nt].x);
                    uint32_t b1 = __float_as_uint(kk2 ? bf[nt].w : bf[nt].y);
#pragma unroll
                    for (int mt = 0; mt < 4; ++mt) {
                        mma_tf32(c[mt][nt][0], c[mt][nt][1], c[mt][nt][2], c[mt][nt][3],
                                 __float_as_uint(af[mt].x), __float_as_uint(af[mt].y),
                                 __float_as_uint(af[mt].z), __float_as_uint(af[mt].w),
                                 b0, b1);
                    }
                }
            }
            // interleaved refill of stage 1-s for kt+1
            if (k16 == 0 && more) {
                if (kt > 0)   // empty[1-s]: all warps done reading it (iter kt-1)
                    mbar_wait(sb + 16 + (1 - s) * 8,
                              (uint32_t)(((kt - 1) >> 1) & 1));
                load_half0(1 - s, kt + 1);
            }
            if (k16 == 1 && more) {
                load_half1(1 - s, kt + 1);
                cp_async_arrive(sb + (1 - s) * 8);   // full[1-s]
            }
        }

        // this warp finished all reads of stage s
        if (lane == 0) mbar_arrive(sb + 16 + s * 8);         // empty[s]
    }

    // ---- epilogue: bias + store ----
#pragma unroll
    for (int mt = 0; mt < 4; ++mt) {
        const int row0 = m0 + wm * 64 + mt * 16 + gq;
#pragma unroll
        for (int nt = 0; nt < 8; ++nt) {
            const int col = n0 + wn * 64 + nt * 8 + 2 * tg;
            const float2 bv = *reinterpret_cast<const float2*>(g_bias + col);
            float2 v0, v1;
            v0.x = c[mt][nt][0] + bv.x;
            v0.y = c[mt][nt][1] + bv.y;
            v1.x = c[mt][nt][2] + bv.x;
            v1.y = c[mt][nt][3] + bv.y;
            *reinterpret_cast<float2*>(out + (size_t)row0 * OUT_F + col) = v0;
            *reinterpret_cast<float2*>(out + (size_t)(row0 + 8) * OUT_F + col) = v1;
        }
    }
}

// ============================================================
// Launch
// ============================================================
extern "C" void kernel_launch(void* const* d_in, const int* in_sizes, int n_in,
                              void* d_out, int out_size) {
    const float* x    = (const float*)d_in[0];
    const float* wmu  = (const float*)d_in[1];
    const float* wlv  = (const float*)d_in[2];
    const float* bmu  = (const float*)d_in[3];
    const float* blv  = (const float*)d_in[4];
    const float* weps = (const float*)d_in[5];
    const float* beps = (const float*)d_in[6];
    float* out = (float*)d_out;

    prep_x_pack<<<32768, 256>>>(x);
    prep_w_pack<<<16384, 256>>>(wmu, wlv, weps);
    prep_bias_kernel<<<16, 256>>>(bmu, blv, beps);

    cudaFuncSetAttribute(gemm_kernel,
                         cudaFuncAttributeMaxDynamicSharedMemorySize, SMEM_TOTAL);
    gemm_kernel<<<NPM * NPN, THREADS, SMEM_TOTAL>>>(out);
}

// round 10
// speedup vs baseline: 1.4185x; 1.0164x over previous
#include <cuda_runtime.h>
#include <cuda_bf16.h>
#include <stdint.h>

// ============================================================
// Problem dims
// ============================================================
#define IN_F  4096
#define OUT_F 4096
#define BATCH 8192

#define BM 256
#define BN 128
#define BK 32
#define NK (IN_F / BK)          // 128 k-tiles
#define NPM (BATCH / BM)        // 32
#define NPN (OUT_F / BN)        // 32
#define TILE_GROUP 8
#define THREADS 256             // 8 warps: 4 (M) x 2 (N), warp tile 64x64
#define STAGES 4

#define NK8  (IN_F / 8)         // 512 k8 groups per row
#define NK16 (IN_F / 16)        // 256 k16 groups per row

// SMEM: [0..32) full mbar[4], [32..64) empty mbar[4], buffers at 128
#define SM_BUF0 128
#define SM_A_BYTES 32768
#define SM_B_BYTES 16384
#define STAGE_BYTES (SM_A_BYTES + SM_B_BYTES)        // 49152
#define SMEM_TOTAL (SM_BUF0 + STAGES * STAGE_BYTES)  // 196736

// ============================================================
// Scratch
// ============================================================
__device__ float4 g_XP[(size_t)(BATCH / 16) * NK8 * 32];
__device__ float4 g_WP[(size_t)(OUT_F / 8) * NK16 * 32];
__device__ float  g_bias[OUT_F];

// ============================================================
// Helpers
// ============================================================
__device__ __forceinline__ float rnd_tf32(float f) {
    float r;
    asm("cvt.rna.tf32.f32 %0, %1;" : "=f"(r) : "f"(f));
    return r;
}

__device__ __forceinline__ uint32_t smem_u32(const void* p) {
    uint32_t a;
    asm("{ .reg .u64 t; cvta.to.shared.u64 t, %1; cvt.u32.u64 %0, t; }"
        : "=r"(a) : "l"(p));
    return a;
}

__device__ __forceinline__ void cp16(uint32_t saddr, const void* gptr) {
    asm volatile("cp.async.cg.shared.global [%0], [%1], 16;\n"
                 :: "r"(saddr), "l"(gptr));
}

__device__ __forceinline__ void mbar_init(uint32_t a, uint32_t cnt) {
    asm volatile("mbarrier.init.shared.b64 [%0], %1;" :: "r"(a), "r"(cnt) : "memory");
}
__device__ __forceinline__ void mbar_arrive(uint32_t a) {
    asm volatile("mbarrier.arrive.shared.b64 _, [%0];" :: "r"(a) : "memory");
}
__device__ __forceinline__ void mbar_wait(uint32_t addr, uint32_t parity) {
    asm volatile(
        "{\n\t.reg .pred P;\n\t"
        "WAIT_%=:\n\t"
        "mbarrier.try_wait.parity.acquire.cta.shared::cta.b64 P, [%0], %1, 0x989680;\n\t"
        "@P bra.uni DONE_%=;\n\t"
        "bra.uni WAIT_%=;\n\t"
        "DONE_%=:\n\t}"
        :: "r"(addr), "r"(parity) : "memory");
}
// signal mbar when all prior cp.async of this thread have completed
__device__ __forceinline__ void cp_async_arrive(uint32_t a) {
    asm volatile("cp.async.mbarrier.arrive.noinc.shared.b64 [%0];"
                 :: "r"(a) : "memory");
}

__device__ __forceinline__ void mma_tf32(float& c0, float& c1, float& c2, float& c3,
                                         uint32_t a0, uint32_t a1, uint32_t a2, uint32_t a3,
                                         uint32_t b0, uint32_t b1) {
    asm volatile(
        "mma.sync.aligned.m16n8k8.row.col.f32.tf32.tf32.f32 "
        "{%0,%1,%2,%3}, {%4,%5,%6,%7}, {%8,%9}, {%0,%1,%2,%3};"
        : "+f"(c0), "+f"(c1), "+f"(c2), "+f"(c3)
        : "r"(a0), "r"(a1), "r"(a2), "r"(a3), "r"(b0), "r"(b1));
}

// ============================================================
// Prep: materialize + tf32-round + pack into fragment order
// ============================================================
__global__ void prep_x_pack(const float* __restrict__ x) {
    size_t i = (size_t)blockIdx.x * blockDim.x + threadIdx.x;  // 8388608
    int row16 = (int)(i >> 14);
    int rem   = (int)(i & 16383);
    int k8    = rem >> 5;
    int lane  = rem & 31;
    int g = lane >> 2, t = lane & 3;
    const float* p0 = x + (size_t)(row16 * 16 + g) * IN_F + k8 * 8 + t;
    float4 v;
    v.x = rnd_tf32(p0[0]);
    v.y = rnd_tf32(p0[8 * IN_F]);
    v.z = rnd_tf32(p0[4]);
    v.w = rnd_tf32(p0[8 * IN_F + 4]);
    g_XP[i] = v;
}

__global__ void prep_w_pack(const float* __restrict__ mu,
                            const float* __restrict__ lv,
                            const float* __restrict__ eps) {
    size_t i = (size_t)blockIdx.x * blockDim.x + threadIdx.x;  // 4194304
    int col8 = (int)(i >> 13);
    int rem  = (int)(i & 8191);
    int k16  = rem >> 5;
    int lane = rem & 31;
    int g = lane >> 2, t = lane & 3;
    size_t base = (size_t)(col8 * 8 + g) * IN_F + k16 * 16 + t;
    float4 v;
#pragma unroll
    for (int j = 0; j < 4; ++j) {
        size_t a = base + (j & 1) * 4 + (j >> 1) * 8;
        float w = mu[a] + eps[a] * __expf(0.5f * lv[a]);
        (&v.x)[j] = rnd_tf32(w);
    }
    g_WP[i] = v;
}

__global__ void prep_bias_kernel(const float* __restrict__ bmu,
                                 const float* __restrict__ blv,
                                 const float* __restrict__ beps) {
    int i = blockIdx.x * blockDim.x + threadIdx.x;
    if (i < OUT_F) g_bias[i] = bmu[i] + beps[i] * __expf(0.5f * blv[i]);
}

// ============================================================
// GEMM: C[256,128] per CTA, 256 threads (8 warps = 4 x 2)
// warp tile 64 x 64, BK=32, 4-stage pipeline with refill issued
// 2 iterations ahead -> warp drift window of 2 k-tiles.
// No __syncthreads in mainloop.
// ============================================================
__global__ void __launch_bounds__(THREADS, 1) gemm_kernel(float* __restrict__ out) {
    extern __shared__ char smem[];
    const uint32_t sb = smem_u32(smem);
    const int tid = threadIdx.x;
    const int wid = tid >> 5;
    const int lane = tid & 31;
    const int wm = wid >> 1;      // 0..3  (M, 64 rows)
    const int wn = wid & 1;       // 0..1  (N, 64 cols)
    const int gq = lane >> 2;
    const int tg = lane & 3;

    int pid = blockIdx.x;
    int grp = pid / (TILE_GROUP * NPN);
    int pin = pid % (TILE_GROUP * NPN);
    int pm  = grp * TILE_GROUP + (pin % TILE_GROUP);
    int pn  = pin / TILE_GROUP;
    const int m0 = pm * BM;
    const int n0 = pn * BN;
    const int m016 = m0 >> 4;
    const int n08  = n0 >> 3;

    // full[s] at sb + s*8, empty[s] at sb + 32 + s*8
    if (tid == 0) {
#pragma unroll
        for (int s = 0; s < STAGES; ++s) {
            mbar_init(sb + s * 8, 256);
            mbar_init(sb + 32 + s * 8, 8);
        }
    }
    __syncthreads();

    // ---- loaders: A = 8 cp16/thread, B = 4 cp16/thread ----
    auto load_A = [&](int s, int kt) {
        const uint32_t abase = sb + SM_BUF0 + (uint32_t)s * STAGE_BYTES;
        const int kt4 = kt * 4;
#pragma unroll
        for (int t = 0; t < 8; ++t) {            // 2048 chunks
            int ca = tid + t * THREADS;
            int r16l = ca >> 7;                  // 128 chunks per row16 group
            int inner = ca & 127;                // k8l*32 + lane
            size_t gidx = ((size_t)(m016 + r16l) * NK8 + kt4 + (inner >> 5)) * 32
                          + (inner & 31);
            cp16(abase + (uint32_t)ca * 16u, g_XP + gidx);
        }
    };
    auto load_B = [&](int s, int kt) {
        const uint32_t bbase = sb + SM_BUF0 + (uint32_t)s * STAGE_BYTES + SM_A_BYTES;
        const int kt2 = kt * 2;
#pragma unroll
        for (int t = 0; t < 4; ++t) {            // 1024 chunks
            int cb = tid + t * THREADS;
            int c8l = cb >> 6;                   // 64 chunks per col8 group
            int inner = cb & 63;                 // k16l*32 + lane
            size_t gidx = ((size_t)(n08 + c8l) * NK16 + kt2 + (inner >> 5)) * 32
                          + (inner & 31);
            cp16(bbase + (uint32_t)cb * 16u, g_WP + gidx);
        }
    };

    // prologue: load stages 0 and 1 (kt+2 loads happen in-loop)
    load_A(0, 0); load_B(0, 0); cp_async_arrive(sb + 0);
    load_A(1, 1); load_B(1, 1); cp_async_arrive(sb + 8);

    float c[4][8][4];
#pragma unroll
    for (int mt = 0; mt < 4; ++mt)
#pragma unroll
        for (int nt = 0; nt < 8; ++nt)
#pragma unroll
            for (int j = 0; j < 4; ++j) c[mt][nt][j] = 0.0f;

    for (int kt = 0; kt < NK; ++kt) {
        const int s = kt & 3;
        mbar_wait(sb + s * 8, (uint32_t)((kt >> 2) & 1));   // full[s]

        const float4* sA = reinterpret_cast<const float4*>(
            smem + SM_BUF0 + (size_t)s * STAGE_BYTES);
        const float4* sB = reinterpret_cast<const float4*>(
            smem + SM_BUF0 + (size_t)s * STAGE_BYTES + SM_A_BYTES);

        const bool more2 = (kt + 2 < NK);
        const int s2 = (kt + 2) & 3;

#pragma unroll
        for (int k16 = 0; k16 < 2; ++k16) {
            float4 bf[8];
#pragma unroll
            for (int nt = 0; nt < 8; ++nt)
                bf[nt] = sB[(((wn * 8 + nt) * 2 + k16) * 32) + lane];
#pragma unroll
            for (int kk2 = 0; kk2 < 2; ++kk2) {
                const int kk = k16 * 2 + kk2;
                float4 af[4];
#pragma unroll
                for (int mt = 0; mt < 4; ++mt)
                    af[mt] = sA[(((wm * 4 + mt) * 4 + kk) * 32) + lane];
#pragma unroll
                for (int nt = 0; nt < 8; ++nt) {
                    uint32_t b0 = __float_as_uint(kk2 ? bf[nt].z : bf[nt].x);
                    uint32_t b1 = __float_as_uint(kk2 ? bf[nt].w : bf[nt].y);
#pragma unroll
                    for (int mt = 0; mt < 4; ++mt) {
                        mma_tf32(c[mt][nt][0], c[mt][nt][1], c[mt][nt][2], c[mt][nt][3],
                                 __float_as_uint(af[mt].x), __float_as_uint(af[mt].y),
                                 __float_as_uint(af[mt].z), __float_as_uint(af[mt].w),
                                 b0, b1);
                    }
                }
            }
            // interleaved refill for kt+2 (stage last read at kt-2)
            if (k16 == 0 && more2) {
                if (kt >= 2)
                    mbar_wait(sb + 32 + s2 * 8,
                              (uint32_t)(((kt - 2) >> 2) & 1));  // empty[s2]
                load_A(s2, kt + 2);
            }
            if (k16 == 1 && more2) {
                load_B(s2, kt + 2);
                cp_async_arrive(sb + s2 * 8);                    // full[s2]
            }
        }

        // this warp finished all reads of stage s
        if (lane == 0) mbar_arrive(sb + 32 + s * 8);             // empty[s]
    }

    // ---- epilogue: bias + store ----
#pragma unroll
    for (int mt = 0; mt < 4; ++mt) {
        const int row0 = m0 + wm * 64 + mt * 16 + gq;
#pragma unroll
        for (int nt = 0; nt < 8; ++nt) {
            const int col = n0 + wn * 64 + nt * 8 + 2 * tg;
            const float2 bv = *reinterpret_cast<const float2*>(g_bias + col);
            float2 v0, v1;
            v0.x = c[mt][nt][0] + bv.x;
            v0.y = c[mt][nt][1] + bv.y;
            v1.x = c[mt][nt][2] + bv.x;
            v1.y = c[mt][nt][3] + bv.y;
            *reinterpret_cast<float2*>(out + (size_t)row0 * OUT_F + col) = v0;
            *reinterpret_cast<float2*>(out + (size_t)(row0 + 8) * OUT_F + col) = v1;
        }
    }
}

// ============================================================
// Launch
// ============================================================
extern "C" void kernel_launch(void* const* d_in, const int* in_sizes, int n_in,
                              void* d_out, int out_size) {
    const float* x    = (const float*)d_in[0];
    const float* wmu  = (const float*)d_in[1];
    const float* wlv  = (const float*)d_in[2];
    const float* bmu  = (const float*)d_in[3];
    const float* blv  = (const float*)d_in[4];
    const float* weps = (const float*)d_in[5];
    const float* beps = (const float*)d_in[6];
    float* out = (float*)d_out;

    prep_x_pack<<<32768, 256>>>(x);
    prep_w_pack<<<16384, 256>>>(wmu, wlv, weps);
    prep_bias_kernel<<<16, 256>>>(bmu, blv, beps);

    cudaFuncSetAttribute(gemm_kernel,
                         cudaFuncAttributeMaxDynamicSharedMemorySize, SMEM_TOTAL);
    gemm_kernel<<<NPM * NPN, THREADS, SMEM_TOTAL>>>(out);
}

// round 11
// speedup vs baseline: 1.4539x; 1.0250x over previous
#include <cuda_runtime.h>
#include <cuda_bf16.h>
#include <stdint.h>

// ============================================================
// Problem dims
// ============================================================
#define IN_F  4096
#define OUT_F 4096
#define BATCH 8192

#define BM 256
#define BN 128
#define BK 32
#define NK (IN_F / BK)          // 128 k-tiles
#define NPM (BATCH / BM)        // 32
#define NPN (OUT_F / BN)        // 32
#define TILE_GROUP 8
#define THREADS 256             // 8 warps: 4 (M) x 2 (N), warp tile 64x64
#define STAGES 4

#define NK8  (IN_F / 8)         // 512 k8 groups per row
#define NK16 (IN_F / 16)        // 256 k16 groups per row

// SMEM: [0..32) full mbar[4], [32..64) empty mbar[4], buffers at 128
#define SM_BUF0 128
#define SM_A_BYTES 32768
#define SM_B_BYTES 16384
#define STAGE_BYTES (SM_A_BYTES + SM_B_BYTES)        // 49152
#define SMEM_TOTAL (SM_BUF0 + STAGES * STAGE_BYTES)  // 196736

// per-refill global byte advance
#define A_STEP 2048u            // 4 k8 groups * 32 lanes * 16 B
#define B_STEP 1024u            // 2 k16 groups * 32 lanes * 16 B

// ============================================================
// Scratch
// ============================================================
__device__ float4 g_XP[(size_t)(BATCH / 16) * NK8 * 32];
__device__ float4 g_WP[(size_t)(OUT_F / 8) * NK16 * 32];
__device__ float  g_bias[OUT_F];

// ============================================================
// Helpers
// ============================================================
__device__ __forceinline__ float rnd_tf32(float f) {
    float r;
    asm("cvt.rna.tf32.f32 %0, %1;" : "=f"(r) : "f"(f));
    return r;
}

__device__ __forceinline__ uint32_t smem_u32(const void* p) {
    uint32_t a;
    asm("{ .reg .u64 t; cvta.to.shared.u64 t, %1; cvt.u32.u64 %0, t; }"
        : "=r"(a) : "l"(p));
    return a;
}

__device__ __forceinline__ void cp16(uint32_t saddr, const void* gptr) {
    asm volatile("cp.async.cg.shared.global [%0], [%1], 16;\n"
                 :: "r"(saddr), "l"(gptr));
}

__device__ __forceinline__ void mbar_init(uint32_t a, uint32_t cnt) {
    asm volatile("mbarrier.init.shared.b64 [%0], %1;" :: "r"(a), "r"(cnt) : "memory");
}
__device__ __forceinline__ void mbar_arrive(uint32_t a) {
    asm volatile("mbarrier.arrive.shared.b64 _, [%0];" :: "r"(a) : "memory");
}
__device__ __forceinline__ void mbar_wait(uint32_t addr, uint32_t parity) {
    asm volatile(
        "{\n\t.reg .pred P;\n\t"
        "WAIT_%=:\n\t"
        "mbarrier.try_wait.parity.acquire.cta.shared::cta.b64 P, [%0], %1, 0x989680;\n\t"
        "@P bra.uni DONE_%=;\n\t"
        "bra.uni WAIT_%=;\n\t"
        "DONE_%=:\n\t}"
        :: "r"(addr), "r"(parity) : "memory");
}
// signal mbar when all prior cp.async of this thread have completed
__device__ __forceinline__ void cp_async_arrive(uint32_t a) {
    asm volatile("cp.async.mbarrier.arrive.noinc.shared.b64 [%0];"
                 :: "r"(a) : "memory");
}

__device__ __forceinline__ void mma_tf32(float& c0, float& c1, float& c2, float& c3,
                                         uint32_t a0, uint32_t a1, uint32_t a2, uint32_t a3,
                                         uint32_t b0, uint32_t b1) {
    asm volatile(
        "mma.sync.aligned.m16n8k8.row.col.f32.tf32.tf32.f32 "
        "{%0,%1,%2,%3}, {%4,%5,%6,%7}, {%8,%9}, {%0,%1,%2,%3};"
        : "+f"(c0), "+f"(c1), "+f"(c2), "+f"(c3)
        : "r"(a0), "r"(a1), "r"(a2), "r"(a3), "r"(b0), "r"(b1));
}

// ============================================================
// Prep: materialize + tf32-round + pack into fragment order
// ============================================================
__global__ void prep_x_pack(const float* __restrict__ x) {
    size_t i = (size_t)blockIdx.x * blockDim.x + threadIdx.x;  // 8388608
    int row16 = (int)(i >> 14);
    int rem   = (int)(i & 16383);
    int k8    = rem >> 5;
    int lane  = rem & 31;
    int g = lane >> 2, t = lane & 3;
    const float* p0 = x + (size_t)(row16 * 16 + g) * IN_F + k8 * 8 + t;
    float4 v;
    v.x = rnd_tf32(p0[0]);
    v.y = rnd_tf32(p0[8 * IN_F]);
    v.z = rnd_tf32(p0[4]);
    v.w = rnd_tf32(p0[8 * IN_F + 4]);
    g_XP[i] = v;
}

__global__ void prep_w_pack(const float* __restrict__ mu,
                            const float* __restrict__ lv,
                            const float* __restrict__ eps) {
    size_t i = (size_t)blockIdx.x * blockDim.x + threadIdx.x;  // 4194304
    int col8 = (int)(i >> 13);
    int rem  = (int)(i & 8191);
    int k16  = rem >> 5;
    int lane = rem & 31;
    int g = lane >> 2, t = lane & 3;
    size_t base = (size_t)(col8 * 8 + g) * IN_F + k16 * 16 + t;
    float4 v;
#pragma unroll
    for (int j = 0; j < 4; ++j) {
        size_t a = base + (j & 1) * 4 + (j >> 1) * 8;
        float w = mu[a] + eps[a] * __expf(0.5f * lv[a]);
        (&v.x)[j] = rnd_tf32(w);
    }
    g_WP[i] = v;
}

__global__ void prep_bias_kernel(const float* __restrict__ bmu,
                                 const float* __restrict__ blv,
                                 const float* __restrict__ beps) {
    int i = blockIdx.x * blockDim.x + threadIdx.x;
    if (i < OUT_F) g_bias[i] = bmu[i] + beps[i] * __expf(0.5f * blv[i]);
}

// ============================================================
// GEMM: C[256,128] per CTA, 256 threads (8 warps = 4 x 2)
// warp tile 64 x 64, BK=32, 4-stage pipeline, refill 2 ahead.
// Mainloop unrolled x4 (compile-time stage index); refill global
// addresses strength-reduced to u32 offsets advanced per call.
// ============================================================
__global__ void __launch_bounds__(THREADS, 1) gemm_kernel(float* __restrict__ out) {
    extern __shared__ char smem[];
    const uint32_t sb = smem_u32(smem);
    const int tid = threadIdx.x;
    const int wid = tid >> 5;
    const int lane = tid & 31;
    const int wm = wid >> 1;      // 0..3  (M, 64 rows)
    const int wn = wid & 1;       // 0..1  (N, 64 cols)
    const int gq = lane >> 2;
    const int tg = lane & 3;

    int pid = blockIdx.x;
    int grp = pid / (TILE_GROUP * NPN);
    int pin = pid % (TILE_GROUP * NPN);
    int pm  = grp * TILE_GROUP + (pin % TILE_GROUP);
    int pn  = pin / TILE_GROUP;
    const int m0 = pm * BM;
    const int n0 = pn * BN;
    const int m016 = m0 >> 4;
    const int n08  = n0 >> 3;

    // full[s] at sb + s*8, empty[s] at sb + 32 + s*8
    if (tid == 0) {
#pragma unroll
        for (int s = 0; s < STAGES; ++s) {
            mbar_init(sb + s * 8, 256);
            mbar_init(sb + 32 + s * 8, 8);
        }
    }
    __syncthreads();

    // ---- strength-reduced refill offsets (byte offsets, advance per call) ----
    uint32_t offA[8], offB[4];
#pragma unroll
    for (int t = 0; t < 8; ++t) {
        int ca = tid + t * THREADS;
        int r16l = ca >> 7;
        int inner = ca & 127;
        offA[t] = (uint32_t)(((((m016 + r16l) * NK8) + (inner >> 5)) * 32
                              + (inner & 31)) * 16);
    }
#pragma unroll
    for (int t = 0; t < 4; ++t) {
        int cb = tid + t * THREADS;
        int c8l = cb >> 6;
        int inner = cb & 63;
        offB[t] = (uint32_t)(((((n08 + c8l) * NK16) + (inner >> 5)) * 32
                              + (inner & 31)) * 16);
    }
    const char* gXb = (const char*)g_XP;
    const char* gWb = (const char*)g_WP;

    auto load_A = [&](uint32_t abase) {
#pragma unroll
        for (int t = 0; t < 8; ++t)
            cp16(abase + (uint32_t)(tid + t * THREADS) * 16u, gXb + offA[t]);
#pragma unroll
        for (int t = 0; t < 8; ++t) offA[t] += A_STEP;
    };
    auto load_B = [&](uint32_t bbase) {
#pragma unroll
        for (int t = 0; t < 4; ++t)
            cp16(bbase + (uint32_t)(tid + t * THREADS) * 16u, gWb + offB[t]);
#pragma unroll
        for (int t = 0; t < 4; ++t) offB[t] += B_STEP;
    };

    // prologue: load stages 0 and 1
    load_A(sb + SM_BUF0);
    load_B(sb + SM_BUF0 + SM_A_BYTES);
    cp_async_arrive(sb + 0);
    load_A(sb + SM_BUF0 + STAGE_BYTES);
    load_B(sb + SM_BUF0 + STAGE_BYTES + SM_A_BYTES);
    cp_async_arrive(sb + 8);

    float c[4][8][4];
#pragma unroll
    for (int mt = 0; mt < 4; ++mt)
#pragma unroll
        for (int nt = 0; nt < 8; ++nt)
#pragma unroll
            for (int j = 0; j < 4; ++j) c[mt][nt][j] = 0.0f;

    for (int ko = 0; ko < NK; ko += 4) {
        const uint32_t op = (uint32_t)((ko >> 2) & 1);
        const uint32_t opx = op ^ 1u;
#pragma unroll
        for (int si = 0; si < 4; ++si) {
            const int kt = ko + si;
            const uint32_t sbase = sb + SM_BUF0 + (uint32_t)(si * STAGE_BYTES);
            mbar_wait(sb + si * 8, op);               // full[si]

            const float4* sA = reinterpret_cast<const float4*>(
                smem + SM_BUF0 + (size_t)(si * STAGE_BYTES));
            const float4* sB = reinterpret_cast<const float4*>(
                smem + SM_BUF0 + (size_t)(si * STAGE_BYTES) + SM_A_BYTES);

            const int s2 = (si + 2) & 3;
            const uint32_t s2base = sb + SM_BUF0 + (uint32_t)(s2 * STAGE_BYTES);
            const bool more2 = (kt + 2 < NK);
            // empty[s2] parity: stage s2 last read at kt-2
            const uint32_t ep = (si < 2) ? opx : op;

#pragma unroll
            for (int k16 = 0; k16 < 2; ++k16) {
                float4 bf[8];
#pragma unroll
                for (int nt = 0; nt < 8; ++nt)
                    bf[nt] = sB[(((wn * 8 + nt) * 2 + k16) * 32) + lane];
#pragma unroll
                for (int kk2 = 0; kk2 < 2; ++kk2) {
                    const int kk = k16 * 2 + kk2;
                    float4 af[4];
#pragma unroll
                    for (int mt = 0; mt < 4; ++mt)
                        af[mt] = sA[(((wm * 4 + mt) * 4 + kk) * 32) + lane];
#pragma unroll
                    for (int nt = 0; nt < 8; ++nt) {
                        uint32_t b0 = __float_as_uint(kk2 ? bf[nt].z : bf[nt].x);
                        uint32_t b1 = __float_as_uint(kk2 ? bf[nt].w : bf[nt].y);
#pragma unroll
                        for (int mt = 0; mt < 4; ++mt) {
                            mma_tf32(c[mt][nt][0], c[mt][nt][1],
                                     c[mt][nt][2], c[mt][nt][3],
                                     __float_as_uint(af[mt].x), __float_as_uint(af[mt].y),
                                     __float_as_uint(af[mt].z), __float_as_uint(af[mt].w),
                                     b0, b1);
                        }
                    }
                }
                // interleaved refill for kt+2
                if (k16 == 0 && more2) {
                    if (kt >= 2)
                        mbar_wait(sb + 32 + s2 * 8, ep);   // empty[s2]
                    load_A(s2base);
                }
                if (k16 == 1 && more2) {
                    load_B(s2base + SM_A_BYTES);
                    cp_async_arrive(sb + s2 * 8);          // full[s2]
                }
            }

            // this warp finished all reads of stage si
            if (lane == 0) mbar_arrive(sb + 32 + si * 8);  // empty[si]
        }
    }

    // ---- epilogue: bias + store ----
#pragma unroll
    for (int mt = 0; mt < 4; ++mt) {
        const int row0 = m0 + wm * 64 + mt * 16 + gq;
#pragma unroll
        for (int nt = 0; nt < 8; ++nt) {
            const int col = n0 + wn * 64 + nt * 8 + 2 * tg;
            const float2 bv = *reinterpret_cast<const float2*>(g_bias + col);
            float2 v0, v1;
            v0.x = c[mt][nt][0] + bv.x;
            v0.y = c[mt][nt][1] + bv.y;
            v1.x = c[mt][nt][2] + bv.x;
            v1.y = c[mt][nt][3] + bv.y;
            *reinterpret_cast<float2*>(out + (size_t)row0 * OUT_F + col) = v0;
            *reinterpret_cast<float2*>(out + (size_t)(row0 + 8) * OUT_F + col) = v1;
        }
    }
}

// ============================================================
// Launch
// ============================================================
extern "C" void kernel_launch(void* const* d_in, const int* in_sizes, int n_in,
                              void* d_out, int out_size) {
    const float* x    = (const float*)d_in[0];
    const float* wmu  = (const float*)d_in[1];
    const float* wlv  = (const float*)d_in[2];
    const float* bmu  = (const float*)d_in[3];
    const float* blv  = (const float*)d_in[4];
    const float* weps = (const float*)d_in[5];
    const float* beps = (const float*)d_in[6];
    float* out = (float*)d_out;

    prep_x_pack<<<32768, 256>>>(x);
    prep_w_pack<<<16384, 256>>>(wmu, wlv, weps);
    prep_bias_kernel<<<16, 256>>>(bmu, blv, beps);

    cudaFuncSetAttribute(gemm_kernel,
                         cudaFuncAttributeMaxDynamicSharedMemorySize, SMEM_TOTAL);
    gemm_kernel<<<NPM * NPN, THREADS, SMEM_TOTAL>>>(out);
}

// round 12
// speedup vs baseline: 1.4598x; 1.0041x over previous
#include <cuda_runtime.h>
#include <cuda_bf16.h>
#include <stdint.h>

// ============================================================
// Problem dims
// ============================================================
#define IN_F  4096
#define OUT_F 4096
#define BATCH 8192

#define BM 256
#define BN 128
#define BK 32
#define NK (IN_F / BK)          // 128 k-tiles
#define NPM (BATCH / BM)        // 32
#define NPN (OUT_F / BN)        // 32
#define TILE_GROUP 8
#define THREADS 256             // 8 warps: 4 (M) x 2 (N), warp tile 64x64
#define STAGES 4

#define NK8  (IN_F / 8)         // 512 k8 groups per row
#define NK16 (IN_F / 16)        // 256 k16 groups per row

// SMEM: [0..32) full mbar[4], [32..64) empty mbar[4], buffers at 128
#define SM_BUF0 128
#define SM_A_BYTES 32768
#define SM_B_BYTES 16384
#define STAGE_BYTES (SM_A_BYTES + SM_B_BYTES)        // 49152
#define SMEM_TOTAL (SM_BUF0 + STAGES * STAGE_BYTES)  // 196736

// per-refill global byte advance
#define A_STEP 2048u
#define B_STEP 1024u

// fused prep block ranges (256 threads each)
#define PREP_X_BLOCKS 32768
#define PREP_W_BLOCKS 16384
#define PREP_BLOCKS (PREP_X_BLOCKS + PREP_W_BLOCKS + 16)

// ============================================================
// Scratch
// ============================================================
__device__ float4 g_XP[(size_t)(BATCH / 16) * NK8 * 32];
__device__ float4 g_WP[(size_t)(OUT_F / 8) * NK16 * 32];
__device__ float  g_bias[OUT_F];

// ============================================================
// Helpers
// ============================================================
__device__ __forceinline__ float rnd_tf32(float f) {
    float r;
    asm("cvt.rna.tf32.f32 %0, %1;" : "=f"(r) : "f"(f));
    return r;
}

__device__ __forceinline__ uint32_t smem_u32(const void* p) {
    uint32_t a;
    asm("{ .reg .u64 t; cvta.to.shared.u64 t, %1; cvt.u32.u64 %0, t; }"
        : "=r"(a) : "l"(p));
    return a;
}

__device__ __forceinline__ void cp16(uint32_t saddr, const void* gptr) {
    asm volatile("cp.async.cg.shared.global [%0], [%1], 16;\n"
                 :: "r"(saddr), "l"(gptr));
}

__device__ __forceinline__ void mbar_init(uint32_t a, uint32_t cnt) {
    asm volatile("mbarrier.init.shared.b64 [%0], %1;" :: "r"(a), "r"(cnt) : "memory");
}
__device__ __forceinline__ void mbar_arrive(uint32_t a) {
    asm volatile("mbarrier.arrive.shared.b64 _, [%0];" :: "r"(a) : "memory");
}
__device__ __forceinline__ void mbar_wait(uint32_t addr, uint32_t parity) {
    asm volatile(
        "{\n\t.reg .pred P;\n\t"
        "WAIT_%=:\n\t"
        "mbarrier.try_wait.parity.acquire.cta.shared::cta.b64 P, [%0], %1, 0x989680;\n\t"
        "@P bra.uni DONE_%=;\n\t"
        "bra.uni WAIT_%=;\n\t"
        "DONE_%=:\n\t}"
        :: "r"(addr), "r"(parity) : "memory");
}
__device__ __forceinline__ void cp_async_arrive(uint32_t a) {
    asm volatile("cp.async.mbarrier.arrive.noinc.shared.b64 [%0];"
                 :: "r"(a) : "memory");
}

__device__ __forceinline__ void mma_tf32(float& c0, float& c1, float& c2, float& c3,
                                         uint32_t a0, uint32_t a1, uint32_t a2, uint32_t a3,
                                         uint32_t b0, uint32_t b1) {
    asm volatile(
        "mma.sync.aligned.m16n8k8.row.col.f32.tf32.tf32.f32 "
        "{%0,%1,%2,%3}, {%4,%5,%6,%7}, {%8,%9}, {%0,%1,%2,%3};"
        : "+f"(c0), "+f"(c1), "+f"(c2), "+f"(c3)
        : "r"(a0), "r"(a1), "r"(a2), "r"(a3), "r"(b0), "r"(b1));
}

// ============================================================
// Fused prep: X pack | W materialize+pack | bias, by block range
// ============================================================
__global__ void prep_fused(const float* __restrict__ x,
                           const float* __restrict__ mu,
                           const float* __restrict__ lv,
                           const float* __restrict__ eps,
                           const float* __restrict__ bmu,
                           const float* __restrict__ blv,
                           const float* __restrict__ beps) {
    int bid = blockIdx.x;
    if (bid < PREP_X_BLOCKS) {
        size_t i = (size_t)bid * 256 + threadIdx.x;          // 8388608
        int row16 = (int)(i >> 14);
        int rem   = (int)(i & 16383);
        int k8    = rem >> 5;
        int lane  = rem & 31;
        int g = lane >> 2, t = lane & 3;
        const float* p0 = x + (size_t)(row16 * 16 + g) * IN_F + k8 * 8 + t;
        float4 v;
        v.x = rnd_tf32(p0[0]);
        v.y = rnd_tf32(p0[8 * IN_F]);
        v.z = rnd_tf32(p0[4]);
        v.w = rnd_tf32(p0[8 * IN_F + 4]);
        g_XP[i] = v;
    } else if (bid < PREP_X_BLOCKS + PREP_W_BLOCKS) {
        size_t i = (size_t)(bid - PREP_X_BLOCKS) * 256 + threadIdx.x;  // 4194304
        int col8 = (int)(i >> 13);
        int rem  = (int)(i & 8191);
        int k16  = rem >> 5;
        int lane = rem & 31;
        int g = lane >> 2, t = lane & 3;
        size_t base = (size_t)(col8 * 8 + g) * IN_F + k16 * 16 + t;
        float4 v;
#pragma unroll
        for (int j = 0; j < 4; ++j) {
            size_t a = base + (j & 1) * 4 + (j >> 1) * 8;
            float w = mu[a] + eps[a] * __expf(0.5f * lv[a]);
            (&v.x)[j] = rnd_tf32(w);
        }
        g_WP[i] = v;
    } else {
        int i = (bid - PREP_X_BLOCKS - PREP_W_BLOCKS) * 256 + threadIdx.x;
        if (i < OUT_F) g_bias[i] = bmu[i] + beps[i] * __expf(0.5f * blv[i]);
    }
}

// ============================================================
// GEMM: C[256,128] per CTA, 256 threads (8 warps = 4 x 2)
// warp tile 64 x 64, BK=32, 4-stage pipeline, refill 2 ahead,
// mainloop unrolled x4, B-fragment loads dependency-chained into
// the MMA stream (anti-burst).
// ============================================================
__global__ void __launch_bounds__(THREADS, 1) gemm_kernel(float* __restrict__ out) {
    extern __shared__ char smem[];
    const uint32_t sb = smem_u32(smem);
    const int tid = threadIdx.x;
    const int wid = tid >> 5;
    const int lane = tid & 31;
    const int wm = wid >> 1;      // 0..3  (M, 64 rows)
    const int wn = wid & 1;       // 0..1  (N, 64 cols)
    const int gq = lane >> 2;
    const int tg = lane & 3;

    int pid = blockIdx.x;
    int grp = pid / (TILE_GROUP * NPN);
    int pin = pid % (TILE_GROUP * NPN);
    int pm  = grp * TILE_GROUP + (pin % TILE_GROUP);
    int pn  = pin / TILE_GROUP;
    const int m0 = pm * BM;
    const int n0 = pn * BN;
    const int m016 = m0 >> 4;
    const int n08  = n0 >> 3;

    if (tid == 0) {
#pragma unroll
        for (int s = 0; s < STAGES; ++s) {
            mbar_init(sb + s * 8, 256);
            mbar_init(sb + 32 + s * 8, 8);
        }
    }
    __syncthreads();

    // ---- strength-reduced refill offsets ----
    uint32_t offA[8], offB[4];
#pragma unroll
    for (int t = 0; t < 8; ++t) {
        int ca = tid + t * THREADS;
        int r16l = ca >> 7;
        int inner = ca & 127;
        offA[t] = (uint32_t)(((((m016 + r16l) * NK8) + (inner >> 5)) * 32
                              + (inner & 31)) * 16);
    }
#pragma unroll
    for (int t = 0; t < 4; ++t) {
        int cb = tid + t * THREADS;
        int c8l = cb >> 6;
        int inner = cb & 63;
        offB[t] = (uint32_t)(((((n08 + c8l) * NK16) + (inner >> 5)) * 32
                              + (inner & 31)) * 16);
    }
    const char* gXb = (const char*)g_XP;
    const char* gWb = (const char*)g_WP;

    auto load_A = [&](uint32_t abase) {
#pragma unroll
        for (int t = 0; t < 8; ++t)
            cp16(abase + (uint32_t)(tid + t * THREADS) * 16u, gXb + offA[t]);
#pragma unroll
        for (int t = 0; t < 8; ++t) offA[t] += A_STEP;
    };
    auto load_B = [&](uint32_t bbase) {
#pragma unroll
        for (int t = 0; t < 4; ++t)
            cp16(bbase + (uint32_t)(tid + t * THREADS) * 16u, gWb + offB[t]);
#pragma unroll
        for (int t = 0; t < 4; ++t) offB[t] += B_STEP;
    };

    // prologue: load stages 0 and 1
    load_A(sb + SM_BUF0);
    load_B(sb + SM_BUF0 + SM_A_BYTES);
    cp_async_arrive(sb + 0);
    load_A(sb + SM_BUF0 + STAGE_BYTES);
    load_B(sb + SM_BUF0 + STAGE_BYTES + SM_A_BYTES);
    cp_async_arrive(sb + 8);

    float c[4][8][4];
#pragma unroll
    for (int mt = 0; mt < 4; ++mt)
#pragma unroll
        for (int nt = 0; nt < 8; ++nt)
#pragma unroll
            for (int j = 0; j < 4; ++j) c[mt][nt][j] = 0.0f;

    for (int ko = 0; ko < NK; ko += 4) {
        const uint32_t op = (uint32_t)((ko >> 2) & 1);
        const uint32_t opx = op ^ 1u;
#pragma unroll
        for (int si = 0; si < 4; ++si) {
            const int kt = ko + si;
            mbar_wait(sb + si * 8, op);               // full[si]

            const float4* sA = reinterpret_cast<const float4*>(
                smem + SM_BUF0 + (size_t)(si * STAGE_BYTES));
            const float4* sB = reinterpret_cast<const float4*>(
                smem + SM_BUF0 + (size_t)(si * STAGE_BYTES) + SM_A_BYTES);

            const int s2 = (si + 2) & 3;
            const uint32_t s2base = sb + SM_BUF0 + (uint32_t)(s2 * STAGE_BYTES);
            const bool more2 = (kt + 2 < NK);
            const uint32_t ep = (si < 2) ? opx : op;

#pragma unroll
            for (int k16 = 0; k16 < 2; ++k16) {
                // ---- kk2 = 0: load af, then per-nt {load bf, 4 MMAs} ----
                float4 af[4];
#pragma unroll
                for (int mt = 0; mt < 4; ++mt)
                    af[mt] = sA[(((wm * 4 + mt) * 4 + k16 * 2) * 32) + lane];
                float4 bf[8];
#pragma unroll
                for (int nt = 0; nt < 8; ++nt) {
                    bf[nt] = sB[(((wn * 8 + nt) * 2 + k16) * 32) + lane];
                    uint32_t b0 = __float_as_uint(bf[nt].x);
                    uint32_t b1 = __float_as_uint(bf[nt].y);
#pragma unroll
                    for (int mt = 0; mt < 4; ++mt) {
                        mma_tf32(c[mt][nt][0], c[mt][nt][1],
                                 c[mt][nt][2], c[mt][nt][3],
                                 __float_as_uint(af[mt].x), __float_as_uint(af[mt].y),
                                 __float_as_uint(af[mt].z), __float_as_uint(af[mt].w),
                                 b0, b1);
                    }
                }
                // ---- kk2 = 1: reload af, bf already in regs ----
#pragma unroll
                for (int mt = 0; mt < 4; ++mt)
                    af[mt] = sA[(((wm * 4 + mt) * 4 + k16 * 2 + 1) * 32) + lane];
#pragma unroll
                for (int nt = 0; nt < 8; ++nt) {
                    uint32_t b0 = __float_as_uint(bf[nt].z);
                    uint32_t b1 = __float_as_uint(bf[nt].w);
#pragma unroll
                    for (int mt = 0; mt < 4; ++mt) {
                        mma_tf32(c[mt][nt][0], c[mt][nt][1],
                                 c[mt][nt][2], c[mt][nt][3],
                                 __float_as_uint(af[mt].x), __float_as_uint(af[mt].y),
                                 __float_as_uint(af[mt].z), __float_as_uint(af[mt].w),
                                 b0, b1);
                    }
                }
                // interleaved refill for kt+2
                if (k16 == 0 && more2) {
                    if (kt >= 2)
                        mbar_wait(sb + 32 + s2 * 8, ep);   // empty[s2]
                    load_A(s2base);
                }
                if (k16 == 1 && more2) {
                    load_B(s2base + SM_A_BYTES);
                    cp_async_arrive(sb + s2 * 8);          // full[s2]
                }
            }

            if (lane == 0) mbar_arrive(sb + 32 + si * 8);  // empty[si]
        }
    }

    // ---- epilogue: bias + store ----
#pragma unroll
    for (int mt = 0; mt < 4; ++mt) {
        const int row0 = m0 + wm * 64 + mt * 16 + gq;
#pragma unroll
        for (int nt = 0; nt < 8; ++nt) {
            const int col = n0 + wn * 64 + nt * 8 + 2 * tg;
            const float2 bv = *reinterpret_cast<const float2*>(g_bias + col);
            float2 v0, v1;
            v0.x = c[mt][nt][0] + bv.x;
            v0.y = c[mt][nt][1] + bv.y;
            v1.x = c[mt][nt][2] + bv.x;
            v1.y = c[mt][nt][3] + bv.y;
            *reinterpret_cast<float2*>(out + (size_t)row0 * OUT_F + col) = v0;
            *reinterpret_cast<float2*>(out + (size_t)(row0 + 8) * OUT_F + col) = v1;
        }
    }
}

// ============================================================
// Launch
// ============================================================
extern "C" void kernel_launch(void* const* d_in, const int* in_sizes, int n_in,
                              void* d_out, int out_size) {
    const float* x    = (const float*)d_in[0];
    const float* wmu  = (const float*)d_in[1];
    const float* wlv  = (const float*)d_in[2];
    const float* bmu  = (const float*)d_in[3];
    const float* blv  = (const float*)d_in[4];
    const float* weps = (const float*)d_in[5];
    const float* beps = (const float*)d_in[6];
    float* out = (float*)d_out;

    prep_fused<<<PREP_BLOCKS, 256>>>(x, wmu, wlv, weps, bmu, blv, beps);

    cudaFuncSetAttribute(gemm_kernel,
                         cudaFuncAttributeMaxDynamicSharedMemorySize, SMEM_TOTAL);
    gemm_kernel<<<NPM * NPN, THREADS, SMEM_TOTAL>>>(out);
}